// round 1
// baseline (speedup 1.0000x reference)
#include <cuda_runtime.h>

// ---------------- problem constants (static shapes) ----------------
#define HEADS 6
#define LW    144            // window length (2*6*12)
#define HD    32             // head dim
#define CDIM  192
#define NW    64             // bias-sharing groups
#define WWINS 15
#define BTOT  960            // total windows
#define M1    (BTOT*LW)      // 138240 rows
#define N1    576
#define K1    192
#define TABNH (NW*HEADS)     // 384

// ---------------- scratch (device globals; no allocations) ----------------
__device__ float g_q[(size_t)BTOT*HEADS*LW*HD];
__device__ float g_k[(size_t)BTOT*HEADS*LW*HD];
__device__ float g_v[(size_t)BTOT*HEADS*LW*HD];
__device__ float g_bias[(size_t)NW*HEADS*LW*LW];
__device__ float g_att[(size_t)BTOT*LW*CDIM];

// ---------------- helpers ----------------
__device__ __forceinline__ float tf32r(float x) {
    unsigned int u;
    asm("cvt.rna.tf32.f32 %0, %1;" : "=r"(u) : "f"(x));
    return __uint_as_float(u);
}

__device__ __forceinline__ void mma8(float c[4],
                                     unsigned a0, unsigned a1, unsigned a2, unsigned a3,
                                     unsigned b0, unsigned b1) {
    asm volatile(
        "mma.sync.aligned.m16n8k8.row.col.f32.tf32.tf32.f32 "
        "{%0,%1,%2,%3}, {%4,%5,%6,%7}, {%8,%9}, {%0,%1,%2,%3};\n"
        : "+f"(c[0]), "+f"(c[1]), "+f"(c[2]), "+f"(c[3])
        : "r"(a0), "r"(a1), "r"(a2), "r"(a3), "r"(b0), "r"(b1));
}

// ---------------- kernel 0: expand bias table ----------------
// g_bias[nw][h][l][m] = table[pidx[l][m]][nw][h]
__global__ __launch_bounds__(256) void k_bias(const float* __restrict__ table,
                                              const int* __restrict__ pidx) {
    int idx = blockIdx.x * 256 + threadIdx.x;
    if (idx >= NW * HEADS * LW * LW) return;
    int m  = idx % LW;
    int l  = (idx / LW) % LW;
    int h  = (idx / (LW * LW)) % HEADS;
    int nw = idx / (LW * LW * HEADS);
    g_bias[idx] = table[(size_t)pidx[l * LW + m] * TABNH + nw * HEADS + h];
}

// ---------------- kernel 1: QKV = x @ W1 + b1, scatter to Q/K/V ----------------
// M=138240, K=192, N=576. Block tile 128x64, 256 threads (8 warps, 4x2).
__global__ __launch_bounds__(256) void k_qkv(const float* __restrict__ x,
                                             const float* __restrict__ W1,
                                             const float* __restrict__ b1) {
    __shared__ float As[128][36];   // [m][k], stride 36 (==4 mod 8 -> conflict-free frags)
    __shared__ float Bs[32][68];    // [k][n]

    const int tid  = threadIdx.x;
    const int lane = tid & 31, wid = tid >> 5;
    const int g = lane >> 2, tg = lane & 3;
    const int wm = wid >> 1, wn = wid & 1;
    const int mblk = blockIdx.y * 128;
    const int nblk = blockIdx.x * 64;

    float acc[2][4][4];
#pragma unroll
    for (int i = 0; i < 2; i++)
#pragma unroll
        for (int j = 0; j < 4; j++)
#pragma unroll
            for (int r = 0; r < 4; r++) acc[i][j][r] = 0.f;

    for (int k0 = 0; k0 < K1; k0 += 32) {
#pragma unroll
        for (int i = 0; i < 4; i++) {           // A tile: 128x32 = 1024 float4
            int idx = tid + 256 * i;
            int r = idx >> 3, kc = (idx & 7) << 2;
            float4 v = *(const float4*)(x + (size_t)(mblk + r) * K1 + k0 + kc);
            As[r][kc + 0] = tf32r(v.x); As[r][kc + 1] = tf32r(v.y);
            As[r][kc + 2] = tf32r(v.z); As[r][kc + 3] = tf32r(v.w);
        }
#pragma unroll
        for (int i = 0; i < 2; i++) {           // B tile: 32x64 = 512 float4
            int idx = tid + 256 * i;
            int kr = idx >> 4, nc = (idx & 15) << 2;
            float4 v = *(const float4*)(W1 + (size_t)(k0 + kr) * N1 + nblk + nc);
            Bs[kr][nc + 0] = tf32r(v.x); Bs[kr][nc + 1] = tf32r(v.y);
            Bs[kr][nc + 2] = tf32r(v.z); Bs[kr][nc + 3] = tf32r(v.w);
        }
        __syncthreads();
#pragma unroll
        for (int kk = 0; kk < 4; kk++) {
            const int kb = kk * 8;
            unsigned a[2][4], b[4][2];
#pragma unroll
            for (int mi = 0; mi < 2; mi++) {
                int r0 = wm * 32 + mi * 16;
                a[mi][0] = __float_as_uint(As[r0 + g][kb + tg]);
                a[mi][1] = __float_as_uint(As[r0 + g + 8][kb + tg]);
                a[mi][2] = __float_as_uint(As[r0 + g][kb + tg + 4]);
                a[mi][3] = __float_as_uint(As[r0 + g + 8][kb + tg + 4]);
            }
#pragma unroll
            for (int ni = 0; ni < 4; ni++) {
                int c0 = wn * 32 + ni * 8;
                b[ni][0] = __float_as_uint(Bs[kb + tg][c0 + g]);
                b[ni][1] = __float_as_uint(Bs[kb + tg + 4][c0 + g]);
            }
#pragma unroll
            for (int mi = 0; mi < 2; mi++)
#pragma unroll
                for (int ni = 0; ni < 4; ni++)
                    mma8(acc[mi][ni], a[mi][0], a[mi][1], a[mi][2], a[mi][3],
                         b[ni][0], b[ni][1]);
        }
        __syncthreads();
    }

    const float SCALE = 0.17677669529663687f;   // 32^-0.5
#pragma unroll
    for (int mi = 0; mi < 2; mi++)
#pragma unroll
        for (int ni = 0; ni < 4; ni++)
#pragma unroll
            for (int r2 = 0; r2 < 2; r2++) {
                int mrow = mblk + wm * 32 + mi * 16 + g + r2 * 8;
                int n    = nblk + wn * 32 + ni * 8 + tg * 2;
                float v0 = acc[mi][ni][r2 * 2 + 0] + b1[n];
                float v1 = acc[mi][ni][r2 * 2 + 1] + b1[n + 1];
                int which = n / 192;
                int head  = (n % 192) / 32;
                int d     = n & 31;
                int win   = mrow / LW;
                int l     = mrow - win * LW;
                size_t dst = (((size_t)win * HEADS + head) * LW + l) * HD + d;
                if (which == 0) {
                    *(float2*)(g_q + dst) = make_float2(v0 * SCALE, v1 * SCALE);
                } else if (which == 1) {
                    *(float2*)(g_k + dst) = make_float2(v0, v1);
                } else {
                    *(float2*)(g_v + dst) = make_float2(v0, v1);
                }
            }
}

// ---------------- kernel 2: fused attention per (window, head) ----------------
#define SMEM_K2 ((3 * LW * 36 + LW * 148) * 4)   // 147456 bytes

__global__ __launch_bounds__(256) void k_attn(const float* __restrict__ mask) {
    extern __shared__ float sm[];
    float* Qs = sm;                  // [144][36]
    float* Ks = Qs + LW * 36;
    float* Vs = Ks + LW * 36;
    float* Ss = Vs + LW * 36;        // [144][148]

    const int h = blockIdx.x;
    const int w = blockIdx.y;
    const int nw = w / WWINS;
    const int tid = threadIdx.x, lane = tid & 31, wid = tid >> 5;
    const int g = lane >> 2, tg = lane & 3;

    const size_t base = ((size_t)w * HEADS + h) * LW * HD;
    for (int idx = tid; idx < LW * HD / 4; idx += 256) {   // 1152 float4 each
        int l = idx >> 3, dc = (idx & 7) << 2;
        float4 q = *(const float4*)(g_q + base + (size_t)idx * 4);
        float4 k = *(const float4*)(g_k + base + (size_t)idx * 4);
        float4 v = *(const float4*)(g_v + base + (size_t)idx * 4);
        Qs[l * 36 + dc + 0] = tf32r(q.x); Qs[l * 36 + dc + 1] = tf32r(q.y);
        Qs[l * 36 + dc + 2] = tf32r(q.z); Qs[l * 36 + dc + 3] = tf32r(q.w);
        Ks[l * 36 + dc + 0] = tf32r(k.x); Ks[l * 36 + dc + 1] = tf32r(k.y);
        Ks[l * 36 + dc + 2] = tf32r(k.z); Ks[l * 36 + dc + 3] = tf32r(k.w);
        Vs[l * 36 + dc + 0] = tf32r(v.x); Vs[l * 36 + dc + 1] = tf32r(v.y);
        Vs[l * 36 + dc + 2] = tf32r(v.z); Vs[l * 36 + dc + 3] = tf32r(v.w);
    }
    __syncthreads();

    // --- S = Q K^T + bias + mask.  Jobs: 9 (m16) x 6 (n24) = 54 ---
    const float* biasp = g_bias + ((size_t)nw * HEADS + h) * LW * LW;
    const float* maskp = mask + (size_t)w * LW * LW;
    for (int job = wid; job < 54; job += 8) {
        int mt = job / 6, nt = job % 6;
        int m0 = mt * 16, n0 = nt * 24;
        float acc[3][4];
#pragma unroll
        for (int ni = 0; ni < 3; ni++)
#pragma unroll
            for (int r = 0; r < 4; r++) acc[ni][r] = 0.f;
#pragma unroll
        for (int kk = 0; kk < 4; kk++) {
            int kb = kk * 8;
            unsigned a0 = __float_as_uint(Qs[(m0 + g) * 36 + kb + tg]);
            unsigned a1 = __float_as_uint(Qs[(m0 + g + 8) * 36 + kb + tg]);
            unsigned a2 = __float_as_uint(Qs[(m0 + g) * 36 + kb + tg + 4]);
            unsigned a3 = __float_as_uint(Qs[(m0 + g + 8) * 36 + kb + tg + 4]);
#pragma unroll
            for (int ni = 0; ni < 3; ni++) {
                unsigned b0 = __float_as_uint(Ks[(n0 + ni * 8 + g) * 36 + kb + tg]);
                unsigned b1 = __float_as_uint(Ks[(n0 + ni * 8 + g) * 36 + kb + tg + 4]);
                mma8(acc[ni], a0, a1, a2, a3, b0, b1);
            }
        }
#pragma unroll
        for (int ni = 0; ni < 3; ni++)
#pragma unroll
            for (int r2 = 0; r2 < 2; r2++) {
                int l = m0 + g + r2 * 8;
                int mc = n0 + ni * 8 + tg * 2;
                float2 bi = *(const float2*)(biasp + (size_t)l * LW + mc);
                float2 mk = *(const float2*)(maskp + (size_t)l * LW + mc);
                Ss[l * 148 + mc + 0] = acc[ni][r2 * 2 + 0] + bi.x + mk.x;
                Ss[l * 148 + mc + 1] = acc[ni][r2 * 2 + 1] + bi.y + mk.y;
            }
    }
    __syncthreads();

    // --- softmax per row (warp per row, strided) ---
    for (int l = wid; l < LW; l += 8) {
        float vb[5];
        float mx = -1e30f;
#pragma unroll
        for (int i = 0; i < 5; i++) {
            int c = lane + 32 * i;
            vb[i] = (c < LW) ? Ss[l * 148 + c] : -1e30f;
            mx = fmaxf(mx, vb[i]);
        }
#pragma unroll
        for (int o = 16; o; o >>= 1) mx = fmaxf(mx, __shfl_xor_sync(0xffffffffu, mx, o));
        float s = 0.f;
#pragma unroll
        for (int i = 0; i < 5; i++) {
            int c = lane + 32 * i;
            float e = (c < LW) ? __expf(vb[i] - mx) : 0.f;
            vb[i] = e; s += e;
        }
#pragma unroll
        for (int o = 16; o; o >>= 1) s += __shfl_xor_sync(0xffffffffu, s, o);
        float inv = 1.f / s;
#pragma unroll
        for (int i = 0; i < 5; i++) {
            int c = lane + 32 * i;
            if (c < LW) Ss[l * 148 + c] = tf32r(vb[i] * inv);   // RNA round: unbiased PV mma
        }
    }
    __syncthreads();

    // --- O = P V.  Jobs: 9 (m16) x 4 (n8) = 36 ---
    float* outp = g_att + (size_t)w * LW * CDIM + h * HD;
    for (int job = wid; job < 36; job += 8) {
        int mt = job >> 2, nt = job & 3;
        int m0 = mt * 16, n0 = nt * 8;
        float acc[4] = {0.f, 0.f, 0.f, 0.f};
#pragma unroll
        for (int ks = 0; ks < 18; ks++) {
            int kb = ks * 8;
            unsigned a0 = __float_as_uint(Ss[(m0 + g) * 148 + kb + tg]);
            unsigned a1 = __float_as_uint(Ss[(m0 + g + 8) * 148 + kb + tg]);
            unsigned a2 = __float_as_uint(Ss[(m0 + g) * 148 + kb + tg + 4]);
            unsigned a3 = __float_as_uint(Ss[(m0 + g + 8) * 148 + kb + tg + 4]);
            unsigned b0 = __float_as_uint(Vs[(kb + tg) * 36 + n0 + g]);
            unsigned b1 = __float_as_uint(Vs[(kb + tg + 4) * 36 + n0 + g]);
            mma8(acc, a0, a1, a2, a3, b0, b1);
        }
#pragma unroll
        for (int r2 = 0; r2 < 2; r2++) {
            int l = m0 + g + r2 * 8;
            int d = n0 + tg * 2;
            *(float2*)(outp + (size_t)l * CDIM + d) =
                make_float2(acc[r2 * 2], acc[r2 * 2 + 1]);
        }
    }
}

// ---------------- kernel 3: out = att @ W2 + b2 ----------------
// M=138240, K=192, N=192. Block tile 128x64.
__global__ __launch_bounds__(256) void k_proj(const float* __restrict__ W2,
                                              const float* __restrict__ b2,
                                              float* __restrict__ out) {
    __shared__ float As[128][36];
    __shared__ float Bs[32][68];

    const int tid  = threadIdx.x;
    const int lane = tid & 31, wid = tid >> 5;
    const int g = lane >> 2, tg = lane & 3;
    const int wm = wid >> 1, wn = wid & 1;
    const int mblk = blockIdx.y * 128;
    const int nblk = blockIdx.x * 64;

    float acc[2][4][4];
#pragma unroll
    for (int i = 0; i < 2; i++)
#pragma unroll
        for (int j = 0; j < 4; j++)
#pragma unroll
            for (int r = 0; r < 4; r++) acc[i][j][r] = 0.f;

    for (int k0 = 0; k0 < CDIM; k0 += 32) {
#pragma unroll
        for (int i = 0; i < 4; i++) {
            int idx = tid + 256 * i;
            int r = idx >> 3, kc = (idx & 7) << 2;
            float4 v = *(const float4*)(g_att + (size_t)(mblk + r) * CDIM + k0 + kc);
            As[r][kc + 0] = tf32r(v.x); As[r][kc + 1] = tf32r(v.y);
            As[r][kc + 2] = tf32r(v.z); As[r][kc + 3] = tf32r(v.w);
        }
#pragma unroll
        for (int i = 0; i < 2; i++) {
            int idx = tid + 256 * i;
            int kr = idx >> 4, nc = (idx & 15) << 2;
            float4 v = *(const float4*)(W2 + (size_t)(k0 + kr) * CDIM + nblk + nc);
            Bs[kr][nc + 0] = tf32r(v.x); Bs[kr][nc + 1] = tf32r(v.y);
            Bs[kr][nc + 2] = tf32r(v.z); Bs[kr][nc + 3] = tf32r(v.w);
        }
        __syncthreads();
#pragma unroll
        for (int kk = 0; kk < 4; kk++) {
            const int kb = kk * 8;
            unsigned a[2][4], b[4][2];
#pragma unroll
            for (int mi = 0; mi < 2; mi++) {
                int r0 = wm * 32 + mi * 16;
                a[mi][0] = __float_as_uint(As[r0 + g][kb + tg]);
                a[mi][1] = __float_as_uint(As[r0 + g + 8][kb + tg]);
                a[mi][2] = __float_as_uint(As[r0 + g][kb + tg + 4]);
                a[mi][3] = __float_as_uint(As[r0 + g + 8][kb + tg + 4]);
            }
#pragma unroll
            for (int ni = 0; ni < 4; ni++) {
                int c0 = wn * 32 + ni * 8;
                b[ni][0] = __float_as_uint(Bs[kb + tg][c0 + g]);
                b[ni][1] = __float_as_uint(Bs[kb + tg + 4][c0 + g]);
            }
#pragma unroll
            for (int mi = 0; mi < 2; mi++)
#pragma unroll
                for (int ni = 0; ni < 4; ni++)
                    mma8(acc[mi][ni], a[mi][0], a[mi][1], a[mi][2], a[mi][3],
                         b[ni][0], b[ni][1]);
        }
        __syncthreads();
    }

#pragma unroll
    for (int mi = 0; mi < 2; mi++)
#pragma unroll
        for (int ni = 0; ni < 4; ni++)
#pragma unroll
            for (int r2 = 0; r2 < 2; r2++) {
                int mrow = mblk + wm * 32 + mi * 16 + g + r2 * 8;
                int n    = nblk + wn * 32 + ni * 8 + tg * 2;
                float v0 = acc[mi][ni][r2 * 2 + 0] + b2[n];
                float v1 = acc[mi][ni][r2 * 2 + 1] + b2[n + 1];
                *(float2*)(out + (size_t)mrow * CDIM + n) = make_float2(v0, v1);
            }
}

// ---------------- launch ----------------
extern "C" void kernel_launch(void* const* d_in, const int* in_sizes, int n_in,
                              void* d_out, int out_size) {
    const float* x     = (const float*)d_in[0];
    const float* mask  = (const float*)d_in[1];
    const float* W1    = (const float*)d_in[2];
    const float* b1    = (const float*)d_in[3];
    const float* W2    = (const float*)d_in[4];
    const float* b2    = (const float*)d_in[5];
    const float* table = (const float*)d_in[6];
    const int*   pidx  = (const int*)d_in[7];

    cudaFuncSetAttribute(k_attn, cudaFuncAttributeMaxDynamicSharedMemorySize, SMEM_K2);

    k_bias<<<(NW * HEADS * LW * LW + 255) / 256, 256>>>(table, pidx);
    k_qkv<<<dim3(N1 / 64, M1 / 128), 256>>>(x, W1, b1);
    k_attn<<<dim3(HEADS, BTOT), 256, SMEM_K2>>>(mask);
    k_proj<<<dim3(CDIM / 64, M1 / 128), 256>>>(W2, b2, (float*)d_out);
}

// round 2
// speedup vs baseline: 1.2550x; 1.2550x over previous
#include <cuda_runtime.h>
#include <cstdint>

// ---------------- problem constants (static shapes) ----------------
#define HEADS 6
#define LW    144
#define HD    32
#define CDIM  192
#define NW    64
#define WWINS 15
#define BTOT  960
#define M1    (BTOT*LW)      // 138240
#define N1    576
#define K1    192
#define TABNH (NW*HEADS)

// ---------------- scratch (device globals; no allocations) ----------------
__device__ float g_q[(size_t)BTOT*HEADS*LW*HD];
__device__ float g_k[(size_t)BTOT*HEADS*LW*HD];
__device__ float g_v[(size_t)BTOT*HEADS*LW*HD];
__device__ float g_bias[(size_t)NW*HEADS*LW*LW];
__device__ float g_att[(size_t)BTOT*LW*CDIM];

// ---------------- helpers ----------------
__device__ __forceinline__ float tf32r(float x) {
    unsigned int u;
    asm("cvt.rna.tf32.f32 %0, %1;" : "=r"(u) : "f"(x));
    return __uint_as_float(u);
}

__device__ __forceinline__ void mma8(float c[4],
                                     unsigned a0, unsigned a1, unsigned a2, unsigned a3,
                                     unsigned b0, unsigned b1) {
    asm volatile(
        "mma.sync.aligned.m16n8k8.row.col.f32.tf32.tf32.f32 "
        "{%0,%1,%2,%3}, {%4,%5,%6,%7}, {%8,%9}, {%0,%1,%2,%3};\n"
        : "+f"(c[0]), "+f"(c[1]), "+f"(c[2]), "+f"(c[3])
        : "r"(a0), "r"(a1), "r"(a2), "r"(a3), "r"(b0), "r"(b1));
}

__device__ __forceinline__ uint32_t sptr(const float* p) {
    return (uint32_t)__cvta_generic_to_shared(p);
}

__device__ __forceinline__ void ldsm4(unsigned& r0, unsigned& r1, unsigned& r2, unsigned& r3,
                                      uint32_t a) {
    asm volatile("ldmatrix.sync.aligned.m8n8.x4.shared.b16 {%0,%1,%2,%3}, [%4];\n"
                 : "=r"(r0), "=r"(r1), "=r"(r2), "=r"(r3) : "r"(a));
}

// ---------------- kernel 0: expand bias table ----------------
__global__ __launch_bounds__(256) void k_bias(const float* __restrict__ table,
                                              const int* __restrict__ pidx) {
    int idx = blockIdx.x * 256 + threadIdx.x;
    if (idx >= NW * HEADS * LW * LW) return;
    int m  = idx % LW;
    int l  = (idx / LW) % LW;
    int h  = (idx / (LW * LW)) % HEADS;
    int nw = idx / (LW * LW * HEADS);
    g_bias[idx] = table[(size_t)pidx[l * LW + m] * TABNH + nw * HEADS + h];
}

// ---------------- kernel 1: QKV GEMM (double-buffered, ldmatrix A) ----------------
__global__ __launch_bounds__(256) void k_qkv(const float* __restrict__ x,
                                             const float* __restrict__ W1,
                                             const float* __restrict__ b1) {
    __shared__ __align__(16) float As[2][128][36];
    __shared__ __align__(16) float Bs[2][32][68];

    const int tid  = threadIdx.x;
    const int lane = tid & 31, wid = tid >> 5;
    const int g = lane >> 2, tg = lane & 3;
    const int wm = wid >> 1, wn = wid & 1;
    const int mblk = blockIdx.y * 128;
    const int nblk = blockIdx.x * 64;

    float4 ra[4], rb[2];
    // prologue: load k-tile 0
#pragma unroll
    for (int i = 0; i < 4; i++) {
        int idx = tid + 256 * i; int r = idx >> 3, kc = (idx & 7) << 2;
        ra[i] = *(const float4*)(x + (size_t)(mblk + r) * K1 + kc);
    }
#pragma unroll
    for (int i = 0; i < 2; i++) {
        int idx = tid + 256 * i; int kr = idx >> 4, nc = (idx & 15) << 2;
        rb[i] = *(const float4*)(W1 + (size_t)kr * N1 + nblk + nc);
    }
#pragma unroll
    for (int i = 0; i < 4; i++) {
        int idx = tid + 256 * i; int r = idx >> 3, kc = (idx & 7) << 2;
        As[0][r][kc+0]=tf32r(ra[i].x); As[0][r][kc+1]=tf32r(ra[i].y);
        As[0][r][kc+2]=tf32r(ra[i].z); As[0][r][kc+3]=tf32r(ra[i].w);
    }
#pragma unroll
    for (int i = 0; i < 2; i++) {
        int idx = tid + 256 * i; int kr = idx >> 4, nc = (idx & 15) << 2;
        Bs[0][kr][nc+0]=tf32r(rb[i].x); Bs[0][kr][nc+1]=tf32r(rb[i].y);
        Bs[0][kr][nc+2]=tf32r(rb[i].z); Bs[0][kr][nc+3]=tf32r(rb[i].w);
    }
    __syncthreads();

    float acc[2][4][4];
#pragma unroll
    for (int i = 0; i < 2; i++)
#pragma unroll
        for (int j = 0; j < 4; j++)
#pragma unroll
            for (int r = 0; r < 4; r++) acc[i][j][r] = 0.f;

    for (int kt = 0; kt < 6; kt++) {
        const int cur = kt & 1;
        if (kt < 5) {
            const int k0 = (kt + 1) * 32;
#pragma unroll
            for (int i = 0; i < 4; i++) {
                int idx = tid + 256 * i; int r = idx >> 3, kc = (idx & 7) << 2;
                ra[i] = *(const float4*)(x + (size_t)(mblk + r) * K1 + k0 + kc);
            }
#pragma unroll
            for (int i = 0; i < 2; i++) {
                int idx = tid + 256 * i; int kr = idx >> 4, nc = (idx & 15) << 2;
                rb[i] = *(const float4*)(W1 + (size_t)(k0 + kr) * N1 + nblk + nc);
            }
        }
#pragma unroll
        for (int kk = 0; kk < 4; kk++) {
            const int kb = kk * 8;
            unsigned a[2][4], b[4][2];
#pragma unroll
            for (int mi = 0; mi < 2; mi++) {
                int arow = wm * 32 + mi * 16 + (lane & 15);
                int acol = kb + ((lane & 16) ? 4 : 0);
                ldsm4(a[mi][0], a[mi][1], a[mi][2], a[mi][3], sptr(&As[cur][arow][acol]));
            }
#pragma unroll
            for (int ni = 0; ni < 4; ni++) {
                int c0 = wn * 32 + ni * 8;
                b[ni][0] = __float_as_uint(Bs[cur][kb + tg][c0 + g]);
                b[ni][1] = __float_as_uint(Bs[cur][kb + tg + 4][c0 + g]);
            }
#pragma unroll
            for (int mi = 0; mi < 2; mi++)
#pragma unroll
                for (int ni = 0; ni < 4; ni++)
                    mma8(acc[mi][ni], a[mi][0], a[mi][1], a[mi][2], a[mi][3],
                         b[ni][0], b[ni][1]);
        }
        if (kt < 5) {
            const int nxt = cur ^ 1;
#pragma unroll
            for (int i = 0; i < 4; i++) {
                int idx = tid + 256 * i; int r = idx >> 3, kc = (idx & 7) << 2;
                As[nxt][r][kc+0]=tf32r(ra[i].x); As[nxt][r][kc+1]=tf32r(ra[i].y);
                As[nxt][r][kc+2]=tf32r(ra[i].z); As[nxt][r][kc+3]=tf32r(ra[i].w);
            }
#pragma unroll
            for (int i = 0; i < 2; i++) {
                int idx = tid + 256 * i; int kr = idx >> 4, nc = (idx & 15) << 2;
                Bs[nxt][kr][nc+0]=tf32r(rb[i].x); Bs[nxt][kr][nc+1]=tf32r(rb[i].y);
                Bs[nxt][kr][nc+2]=tf32r(rb[i].z); Bs[nxt][kr][nc+3]=tf32r(rb[i].w);
            }
        }
        __syncthreads();
    }

    const float SCALE = 0.17677669529663687f;
#pragma unroll
    for (int mi = 0; mi < 2; mi++)
#pragma unroll
        for (int ni = 0; ni < 4; ni++)
#pragma unroll
            for (int r2 = 0; r2 < 2; r2++) {
                int mrow = mblk + wm * 32 + mi * 16 + g + r2 * 8;
                int n    = nblk + wn * 32 + ni * 8 + tg * 2;
                float v0 = acc[mi][ni][r2 * 2 + 0] + b1[n];
                float v1 = acc[mi][ni][r2 * 2 + 1] + b1[n + 1];
                int which = n / 192;
                int head  = (n % 192) / 32;
                int d     = n & 31;
                int win   = mrow / LW;
                int l     = mrow - win * LW;
                size_t dst = (((size_t)win * HEADS + head) * LW + l) * HD + d;
                if (which == 0) {
                    *(float2*)(g_q + dst) = make_float2(v0 * SCALE, v1 * SCALE);
                } else if (which == 1) {
                    *(float2*)(g_k + dst) = make_float2(v0, v1);
                } else {
                    *(float2*)(g_v + dst) = make_float2(v0, v1);
                }
            }
}

// ---------------- kernel 2: fused attention, 9 warps, two m-halves ----------------
// smem: Ks[144][36] | Vt[32][148] | Qs[80][36] | Ss[80][148]  = 96.25 KB -> 2 blocks/SM
#define SMEM_ATT ((LW*36 + HD*148 + 80*36 + 80*148) * 4)

__global__ __launch_bounds__(288) void k_attn(const float* __restrict__ mask) {
    extern __shared__ __align__(16) float sm[];
    float* Ks = sm;                 // [144][36]
    float* Vt = Ks + LW * 36;       // [32][148]  (V transposed: [d][l])
    float* Qs = Vt + HD * 148;      // [80][36]   (current m-half)
    float* Ss = Qs + 80 * 36;       // [80][148]

    const int h = blockIdx.x;
    const int w = blockIdx.y;
    const int nwi = w / WWINS;
    const int tid = threadIdx.x, lane = tid & 31, wid = tid >> 5;   // wid 0..8
    const int g = lane >> 2, tg = lane & 3;

    const size_t base = ((size_t)w * HEADS + h) * LW * HD;
    const float* biasp = g_bias + ((size_t)nwi * HEADS + h) * LW * LW;
    const float* maskp = mask + (size_t)w * LW * LW;
    float* outp = g_att + (size_t)w * LW * CDIM + h * HD;

    // ---- load K (tf32), V transposed (tf32), Q half0 ----
    for (int idx = tid; idx < LW * HD / 4; idx += 288) {
        int l = idx >> 3, dc = (idx & 7) << 2;
        float4 kk4 = *(const float4*)(g_k + base + (size_t)idx * 4);
        Ks[l*36+dc+0]=tf32r(kk4.x); Ks[l*36+dc+1]=tf32r(kk4.y);
        Ks[l*36+dc+2]=tf32r(kk4.z); Ks[l*36+dc+3]=tf32r(kk4.w);
        float4 vv4 = *(const float4*)(g_v + base + (size_t)idx * 4);
        Vt[(dc+0)*148+l]=tf32r(vv4.x); Vt[(dc+1)*148+l]=tf32r(vv4.y);
        Vt[(dc+2)*148+l]=tf32r(vv4.z); Vt[(dc+3)*148+l]=tf32r(vv4.w);
    }
    for (int idx = tid; idx < 80 * HD / 4; idx += 288) {
        int l = idx >> 3, dc = (idx & 7) << 2;
        float4 q4 = *(const float4*)(g_q + base + (size_t)idx * 4);
        Qs[l*36+dc+0]=tf32r(q4.x); Qs[l*36+dc+1]=tf32r(q4.y);
        Qs[l*36+dc+2]=tf32r(q4.z); Qs[l*36+dc+3]=tf32r(q4.w);
    }
    __syncthreads();

    // ---- preload this warp's K-fragments (n16 columns) -- kept in regs all block ----
    const int n0 = wid * 16;
    unsigned bq[4][4];
    {
        int brow = n0 + (lane & 7) + ((lane & 16) ? 8 : 0);
#pragma unroll
        for (int kk = 0; kk < 4; kk++) {
            int bcol = kk * 8 + ((lane & 8) ? 4 : 0);
            ldsm4(bq[kk][0], bq[kk][1], bq[kk][2], bq[kk][3], sptr(Ks + brow * 36 + bcol));
        }
    }

    // phase lambdas ---------------------------------------------------------
    auto qk_phase = [&](int mb, int mtiles) {
        for (int mt = 0; mt < mtiles; mt++) {
            int m0 = mt * 16;
            unsigned aq[4][4];
            int arow = m0 + (lane & 15);
#pragma unroll
            for (int kk = 0; kk < 4; kk++) {
                int acol = kk * 8 + ((lane & 16) ? 4 : 0);
                ldsm4(aq[kk][0], aq[kk][1], aq[kk][2], aq[kk][3], sptr(Qs + arow * 36 + acol));
            }
            float acc[2][4];
#pragma unroll
            for (int ni = 0; ni < 2; ni++)
#pragma unroll
                for (int r = 0; r < 4; r++) acc[ni][r] = 0.f;
#pragma unroll
            for (int kk = 0; kk < 4; kk++)
#pragma unroll
                for (int ni = 0; ni < 2; ni++)
                    mma8(acc[ni], aq[kk][0], aq[kk][1], aq[kk][2], aq[kk][3],
                         bq[kk][ni*2], bq[kk][ni*2+1]);
#pragma unroll
            for (int ni = 0; ni < 2; ni++)
#pragma unroll
                for (int r2 = 0; r2 < 2; r2++) {
                    int ll = m0 + g + r2 * 8;
                    int lg = mb + ll;
                    int mc = n0 + ni * 8 + tg * 2;
                    float2 bi = *(const float2*)(biasp + (size_t)lg * LW + mc);
                    float2 mk = *(const float2*)(maskp + (size_t)lg * LW + mc);
                    Ss[ll*148+mc]   = acc[ni][r2*2+0] + bi.x + mk.x;
                    Ss[ll*148+mc+1] = acc[ni][r2*2+1] + bi.y + mk.y;
                }
        }
    };

    auto softmax_phase = [&](int rows) {
        for (int l = wid; l < rows; l += 9) {
            float vb[5];
            float mx = -1e30f;
#pragma unroll
            for (int i = 0; i < 5; i++) {
                int c = lane + 32 * i;
                vb[i] = (c < LW) ? Ss[l*148+c] : -1e30f;
                mx = fmaxf(mx, vb[i]);
            }
#pragma unroll
            for (int o = 16; o; o >>= 1) mx = fmaxf(mx, __shfl_xor_sync(0xffffffffu, mx, o));
            float s = 0.f;
#pragma unroll
            for (int i = 0; i < 5; i++) {
                int c = lane + 32 * i;
                float e = (c < LW) ? __expf(vb[i] - mx) : 0.f;
                vb[i] = e; s += e;
            }
#pragma unroll
            for (int o = 16; o; o >>= 1) s += __shfl_xor_sync(0xffffffffu, s, o);
            float inv = 1.f / s;
#pragma unroll
            for (int i = 0; i < 5; i++) {
                int c = lane + 32 * i;
                if (c < LW) Ss[l*148+c] = tf32r(vb[i] * inv);
            }
        }
    };

    auto pv_phase = [&](int mb, int mtiles) {
        for (int job = wid; job < mtiles * 2; job += 9) {
            int mt = job >> 1;
            int d0 = (job & 1) * 16;
            float acc[2][4];
#pragma unroll
            for (int ni = 0; ni < 2; ni++)
#pragma unroll
                for (int r = 0; r < 4; r++) acc[ni][r] = 0.f;
            int arow = mt * 16 + (lane & 15);
            int acol8 = (lane & 16) ? 4 : 0;
            int vrow = d0 + (lane & 7) + ((lane & 16) ? 8 : 0);
            int vcol8 = (lane & 8) ? 4 : 0;
#pragma unroll
            for (int ks = 0; ks < 18; ks++) {
                int kb = ks * 8;
                unsigned a0,a1,a2,a3, b0,b1,b2,b3;
                ldsm4(a0,a1,a2,a3, sptr(Ss + arow * 148 + kb + acol8));
                ldsm4(b0,b1,b2,b3, sptr(Vt + vrow * 148 + kb + vcol8));
                mma8(acc[0], a0,a1,a2,a3, b0,b1);
                mma8(acc[1], a0,a1,a2,a3, b2,b3);
            }
#pragma unroll
            for (int ni = 0; ni < 2; ni++)
#pragma unroll
                for (int r2 = 0; r2 < 2; r2++) {
                    int lg = mb + mt * 16 + g + r2 * 8;
                    int d = d0 + ni * 8 + tg * 2;
                    *(float2*)(outp + (size_t)lg * CDIM + d) =
                        make_float2(acc[ni][r2*2], acc[ni][r2*2+1]);
                }
        }
    };
    // -----------------------------------------------------------------------

    // half 0: rows 0..79 (5 m-tiles)
    qk_phase(0, 5);
    __syncthreads();
    // load Q half1 (Qs now free) concurrently with softmax of half0
    for (int idx = tid; idx < 64 * HD / 4; idx += 288) {
        int l = idx >> 3, dc = (idx & 7) << 2;
        float4 q4 = *(const float4*)(g_q + base + (size_t)(80 * HD) + (size_t)idx * 4);
        Qs[l*36+dc+0]=tf32r(q4.x); Qs[l*36+dc+1]=tf32r(q4.y);
        Qs[l*36+dc+2]=tf32r(q4.z); Qs[l*36+dc+3]=tf32r(q4.w);
    }
    softmax_phase(80);
    __syncthreads();
    pv_phase(0, 5);
    __syncthreads();

    // half 1: rows 80..143 (4 m-tiles)
    qk_phase(80, 4);
    __syncthreads();
    softmax_phase(64);
    __syncthreads();
    pv_phase(80, 4);
}

// ---------------- kernel 3: out-projection GEMM (double-buffered, ldmatrix A) ----------------
__global__ __launch_bounds__(256) void k_proj(const float* __restrict__ W2,
                                              const float* __restrict__ b2,
                                              float* __restrict__ out) {
    __shared__ __align__(16) float As[2][128][36];
    __shared__ __align__(16) float Bs[2][32][68];

    const int tid  = threadIdx.x;
    const int lane = tid & 31, wid = tid >> 5;
    const int g = lane >> 2, tg = lane & 3;
    const int wm = wid >> 1, wn = wid & 1;
    const int mblk = blockIdx.y * 128;
    const int nblk = blockIdx.x * 64;

    float4 ra[4], rb[2];
#pragma unroll
    for (int i = 0; i < 4; i++) {
        int idx = tid + 256 * i; int r = idx >> 3, kc = (idx & 7) << 2;
        ra[i] = *(const float4*)(g_att + (size_t)(mblk + r) * CDIM + kc);
    }
#pragma unroll
    for (int i = 0; i < 2; i++) {
        int idx = tid + 256 * i; int kr = idx >> 4, nc = (idx & 15) << 2;
        rb[i] = *(const float4*)(W2 + (size_t)kr * CDIM + nblk + nc);
    }
#pragma unroll
    for (int i = 0; i < 4; i++) {
        int idx = tid + 256 * i; int r = idx >> 3, kc = (idx & 7) << 2;
        As[0][r][kc+0]=tf32r(ra[i].x); As[0][r][kc+1]=tf32r(ra[i].y);
        As[0][r][kc+2]=tf32r(ra[i].z); As[0][r][kc+3]=tf32r(ra[i].w);
    }
#pragma unroll
    for (int i = 0; i < 2; i++) {
        int idx = tid + 256 * i; int kr = idx >> 4, nc = (idx & 15) << 2;
        Bs[0][kr][nc+0]=tf32r(rb[i].x); Bs[0][kr][nc+1]=tf32r(rb[i].y);
        Bs[0][kr][nc+2]=tf32r(rb[i].z); Bs[0][kr][nc+3]=tf32r(rb[i].w);
    }
    __syncthreads();

    float acc[2][4][4];
#pragma unroll
    for (int i = 0; i < 2; i++)
#pragma unroll
        for (int j = 0; j < 4; j++)
#pragma unroll
            for (int r = 0; r < 4; r++) acc[i][j][r] = 0.f;

    for (int kt = 0; kt < 6; kt++) {
        const int cur = kt & 1;
        if (kt < 5) {
            const int k0 = (kt + 1) * 32;
#pragma unroll
            for (int i = 0; i < 4; i++) {
                int idx = tid + 256 * i; int r = idx >> 3, kc = (idx & 7) << 2;
                ra[i] = *(const float4*)(g_att + (size_t)(mblk + r) * CDIM + k0 + kc);
            }
#pragma unroll
            for (int i = 0; i < 2; i++) {
                int idx = tid + 256 * i; int kr = idx >> 4, nc = (idx & 15) << 2;
                rb[i] = *(const float4*)(W2 + (size_t)(k0 + kr) * CDIM + nblk + nc);
            }
        }
#pragma unroll
        for (int kk = 0; kk < 4; kk++) {
            const int kb = kk * 8;
            unsigned a[2][4], b[4][2];
#pragma unroll
            for (int mi = 0; mi < 2; mi++) {
                int arow = wm * 32 + mi * 16 + (lane & 15);
                int acol = kb + ((lane & 16) ? 4 : 0);
                ldsm4(a[mi][0], a[mi][1], a[mi][2], a[mi][3], sptr(&As[cur][arow][acol]));
            }
#pragma unroll
            for (int ni = 0; ni < 4; ni++) {
                int c0 = wn * 32 + ni * 8;
                b[ni][0] = __float_as_uint(Bs[cur][kb + tg][c0 + g]);
                b[ni][1] = __float_as_uint(Bs[cur][kb + tg + 4][c0 + g]);
            }
#pragma unroll
            for (int mi = 0; mi < 2; mi++)
#pragma unroll
                for (int ni = 0; ni < 4; ni++)
                    mma8(acc[mi][ni], a[mi][0], a[mi][1], a[mi][2], a[mi][3],
                         b[ni][0], b[ni][1]);
        }
        if (kt < 5) {
            const int nxt = cur ^ 1;
#pragma unroll
            for (int i = 0; i < 4; i++) {
                int idx = tid + 256 * i; int r = idx >> 3, kc = (idx & 7) << 2;
                As[nxt][r][kc+0]=tf32r(ra[i].x); As[nxt][r][kc+1]=tf32r(ra[i].y);
                As[nxt][r][kc+2]=tf32r(ra[i].z); As[nxt][r][kc+3]=tf32r(ra[i].w);
            }
#pragma unroll
            for (int i = 0; i < 2; i++) {
                int idx = tid + 256 * i; int kr = idx >> 4, nc = (idx & 15) << 2;
                Bs[nxt][kr][nc+0]=tf32r(rb[i].x); Bs[nxt][kr][nc+1]=tf32r(rb[i].y);
                Bs[nxt][kr][nc+2]=tf32r(rb[i].z); Bs[nxt][kr][nc+3]=tf32r(rb[i].w);
            }
        }
        __syncthreads();
    }

#pragma unroll
    for (int mi = 0; mi < 2; mi++)
#pragma unroll
        for (int ni = 0; ni < 4; ni++)
#pragma unroll
            for (int r2 = 0; r2 < 2; r2++) {
                int mrow = mblk + wm * 32 + mi * 16 + g + r2 * 8;
                int n    = nblk + wn * 32 + ni * 8 + tg * 2;
                float v0 = acc[mi][ni][r2 * 2 + 0] + b2[n];
                float v1 = acc[mi][ni][r2 * 2 + 1] + b2[n + 1];
                *(float2*)(out + (size_t)mrow * CDIM + n) = make_float2(v0, v1);
            }
}

// ---------------- launch ----------------
extern "C" void kernel_launch(void* const* d_in, const int* in_sizes, int n_in,
                              void* d_out, int out_size) {
    const float* x     = (const float*)d_in[0];
    const float* mask  = (const float*)d_in[1];
    const float* W1    = (const float*)d_in[2];
    const float* b1    = (const float*)d_in[3];
    const float* W2    = (const float*)d_in[4];
    const float* b2    = (const float*)d_in[5];
    const float* table = (const float*)d_in[6];
    const int*   pidx  = (const int*)d_in[7];

    cudaFuncSetAttribute(k_attn, cudaFuncAttributeMaxDynamicSharedMemorySize, SMEM_ATT);

    k_bias<<<(NW * HEADS * LW * LW + 255) / 256, 256>>>(table, pidx);
    k_qkv<<<dim3(N1 / 64, M1 / 128), 256>>>(x, W1, b1);
    k_attn<<<dim3(HEADS, BTOT), 288, SMEM_ATT>>>(mask);
    k_proj<<<dim3(CDIM / 64, M1 / 128), 256>>>(W2, b2, (float*)d_out);
}

// round 3
// speedup vs baseline: 1.4449x; 1.1513x over previous
#include <cuda_runtime.h>
#include <cstdint>

// ---------------- problem constants (static shapes) ----------------
#define HEADS 6
#define LW    144
#define HD    32
#define CDIM  192
#define NW    64
#define WWINS 15
#define BTOT  960
#define M1    (BTOT*LW)      // 138240
#define N1    576
#define K1    192
#define TABNH (NW*HEADS)

// ---------------- scratch (device globals; no allocations) ----------------
__device__ float g_q[(size_t)BTOT*HEADS*LW*HD];
__device__ float g_k[(size_t)BTOT*HEADS*LW*HD];
__device__ float g_v[(size_t)BTOT*HEADS*LW*HD];   // stored TRANSPOSED: [w][h][d][l]
__device__ float g_bias[(size_t)NW*HEADS*LW*LW];
__device__ float g_att[(size_t)BTOT*LW*CDIM];

// ---------------- helpers ----------------
__device__ __forceinline__ float tf32r(float x) {
    unsigned int u;
    asm("cvt.rna.tf32.f32 %0, %1;" : "=r"(u) : "f"(x));
    return __uint_as_float(u);
}

__device__ __forceinline__ float4 tf32r4(float4 v) {
    float4 t;
    t.x = tf32r(v.x); t.y = tf32r(v.y); t.z = tf32r(v.z); t.w = tf32r(v.w);
    return t;
}

__device__ __forceinline__ void mma8(float c[4],
                                     unsigned a0, unsigned a1, unsigned a2, unsigned a3,
                                     unsigned b0, unsigned b1) {
    asm volatile(
        "mma.sync.aligned.m16n8k8.row.col.f32.tf32.tf32.f32 "
        "{%0,%1,%2,%3}, {%4,%5,%6,%7}, {%8,%9}, {%0,%1,%2,%3};\n"
        : "+f"(c[0]), "+f"(c[1]), "+f"(c[2]), "+f"(c[3])
        : "r"(a0), "r"(a1), "r"(a2), "r"(a3), "r"(b0), "r"(b1));
}

__device__ __forceinline__ uint32_t sptr(const float* p) {
    return (uint32_t)__cvta_generic_to_shared(p);
}

__device__ __forceinline__ void ldsm4(unsigned& r0, unsigned& r1, unsigned& r2, unsigned& r3,
                                      uint32_t a) {
    asm volatile("ldmatrix.sync.aligned.m8n8.x4.shared.b16 {%0,%1,%2,%3}, [%4];\n"
                 : "=r"(r0), "=r"(r1), "=r"(r2), "=r"(r3) : "r"(a));
}

__device__ __forceinline__ void ldsm2(unsigned& r0, unsigned& r1, uint32_t a) {
    asm volatile("ldmatrix.sync.aligned.m8n8.x2.shared.b16 {%0,%1}, [%2];\n"
                 : "=r"(r0), "=r"(r1) : "r"(a));
}

// ---------------- kernel 0: expand bias table ----------------
__global__ __launch_bounds__(256) void k_bias(const float* __restrict__ table,
                                              const int* __restrict__ pidx) {
    int idx = blockIdx.x * 256 + threadIdx.x;
    if (idx >= NW * HEADS * LW * LW) return;
    int m  = idx % LW;
    int l  = (idx / LW) % LW;
    int h  = (idx / (LW * LW)) % HEADS;
    int nw = idx / (LW * LW * HEADS);
    g_bias[idx] = table[(size_t)pidx[l * LW + m] * TABNH + nw * HEADS + h];
}

// ---------------- kernel 1: QKV GEMM (double-buffered, conflict-free smem) ----------------
__global__ __launch_bounds__(256) void k_qkv(const float* __restrict__ x,
                                             const float* __restrict__ W1,
                                             const float* __restrict__ b1) {
    __shared__ __align__(16) float As[2][128][36];
    __shared__ __align__(16) float Bs[2][32][72];

    const int tid  = threadIdx.x;
    const int lane = tid & 31, wid = tid >> 5;
    const int g = lane >> 2, tg = lane & 3;
    const int wm = wid >> 1, wn = wid & 1;
    const int mblk = blockIdx.y * 128;
    const int nblk = blockIdx.x * 64;

    float4 ra[4], rb[2];
#pragma unroll
    for (int i = 0; i < 4; i++) {
        int idx = tid + 256 * i; int r = idx >> 3, kc = (idx & 7) << 2;
        ra[i] = *(const float4*)(x + (size_t)(mblk + r) * K1 + kc);
    }
#pragma unroll
    for (int i = 0; i < 2; i++) {
        int idx = tid + 256 * i; int kr = idx >> 4, nc = (idx & 15) << 2;
        rb[i] = *(const float4*)(W1 + (size_t)kr * N1 + nblk + nc);
    }
#pragma unroll
    for (int i = 0; i < 4; i++) {
        int idx = tid + 256 * i; int r = idx >> 3, kc = (idx & 7) << 2;
        *(float4*)&As[0][r][kc] = tf32r4(ra[i]);
    }
#pragma unroll
    for (int i = 0; i < 2; i++) {
        int idx = tid + 256 * i; int kr = idx >> 4, nc = (idx & 15) << 2;
        *(float4*)&Bs[0][kr][nc] = tf32r4(rb[i]);
    }
    __syncthreads();

    float acc[2][4][4];
#pragma unroll
    for (int i = 0; i < 2; i++)
#pragma unroll
        for (int j = 0; j < 4; j++)
#pragma unroll
            for (int r = 0; r < 4; r++) acc[i][j][r] = 0.f;

    for (int kt = 0; kt < 6; kt++) {
        const int cur = kt & 1;
        if (kt < 5) {
            const int k0 = (kt + 1) * 32;
#pragma unroll
            for (int i = 0; i < 4; i++) {
                int idx = tid + 256 * i; int r = idx >> 3, kc = (idx & 7) << 2;
                ra[i] = *(const float4*)(x + (size_t)(mblk + r) * K1 + k0 + kc);
            }
#pragma unroll
            for (int i = 0; i < 2; i++) {
                int idx = tid + 256 * i; int kr = idx >> 4, nc = (idx & 15) << 2;
                rb[i] = *(const float4*)(W1 + (size_t)(k0 + kr) * N1 + nblk + nc);
            }
        }
#pragma unroll
        for (int kk = 0; kk < 4; kk++) {
            const int kb = kk * 8;
            unsigned a[2][4], b[4][2];
#pragma unroll
            for (int mi = 0; mi < 2; mi++) {
                int arow = wm * 32 + mi * 16 + (lane & 15);
                int acol = kb + ((lane & 16) ? 4 : 0);
                ldsm4(a[mi][0], a[mi][1], a[mi][2], a[mi][3], sptr(&As[cur][arow][acol]));
            }
#pragma unroll
            for (int ni = 0; ni < 4; ni++) {
                int c0 = wn * 32 + ni * 8;
                b[ni][0] = __float_as_uint(Bs[cur][kb + tg][c0 + g]);
                b[ni][1] = __float_as_uint(Bs[cur][kb + tg + 4][c0 + g]);
            }
#pragma unroll
            for (int mi = 0; mi < 2; mi++)
#pragma unroll
                for (int ni = 0; ni < 4; ni++)
                    mma8(acc[mi][ni], a[mi][0], a[mi][1], a[mi][2], a[mi][3],
                         b[ni][0], b[ni][1]);
        }
        if (kt < 5) {
            const int nxt = cur ^ 1;
#pragma unroll
            for (int i = 0; i < 4; i++) {
                int idx = tid + 256 * i; int r = idx >> 3, kc = (idx & 7) << 2;
                *(float4*)&As[nxt][r][kc] = tf32r4(ra[i]);
            }
#pragma unroll
            for (int i = 0; i < 2; i++) {
                int idx = tid + 256 * i; int kr = idx >> 4, nc = (idx & 15) << 2;
                *(float4*)&Bs[nxt][kr][nc] = tf32r4(rb[i]);
            }
        }
        __syncthreads();
    }

    const float SCALE = 0.17677669529663687f;
#pragma unroll
    for (int mi = 0; mi < 2; mi++)
#pragma unroll
        for (int ni = 0; ni < 4; ni++)
#pragma unroll
            for (int r2 = 0; r2 < 2; r2++) {
                int mrow = mblk + wm * 32 + mi * 16 + g + r2 * 8;
                int n    = nblk + wn * 32 + ni * 8 + tg * 2;
                float v0 = acc[mi][ni][r2 * 2 + 0] + b1[n];
                float v1 = acc[mi][ni][r2 * 2 + 1] + b1[n + 1];
                int which = n / 192;
                int head  = (n % 192) / 32;
                int d     = n & 31;
                int win   = mrow / LW;
                int l     = mrow - win * LW;
                if (which == 0) {
                    size_t dst = (((size_t)win * HEADS + head) * LW + l) * HD + d;
                    *(float2*)(g_q + dst) = make_float2(v0 * SCALE, v1 * SCALE);
                } else if (which == 1) {
                    size_t dst = (((size_t)win * HEADS + head) * LW + l) * HD + d;
                    *(float2*)(g_k + dst) = make_float2(v0, v1);
                } else {
                    // V stored transposed: [w][h][d][l]
                    size_t baset = ((size_t)win * HEADS + head) * (size_t)(HD * LW);
                    g_v[baset + (size_t)d * LW + l]       = v0;
                    g_v[baset + (size_t)(d + 1) * LW + l] = v1;
                }
            }
}

// ---------------- kernel 2: fused attention, 9 warps, 3 chunks of 48 rows ----------------
// smem: Ks[144][36] | Vt[32][148] | Qs[48][36] | Ss[48][148] = 73.25 KB -> 3 blocks/SM
#define SMEM_ATT ((LW*36 + HD*148 + 48*36 + 48*148) * 4)

__global__ __launch_bounds__(288, 3) void k_attn(const float* __restrict__ mask) {
    extern __shared__ __align__(16) float sm[];
    float* Ks = sm;                  // [144][36]
    float* Vt = Ks + LW * 36;        // [32][148]
    float* Qs = Vt + HD * 148;       // [48][36]
    float* Ss = Qs + 48 * 36;        // [48][148]

    const int h = blockIdx.x;
    const int w = blockIdx.y;
    const int nwi = w / WWINS;
    const int tid = threadIdx.x, lane = tid & 31, wid = tid >> 5;   // wid 0..8
    const int g = lane >> 2, tg = lane & 3;

    const size_t base = ((size_t)w * HEADS + h) * LW * HD;
    const float* biasp = g_bias + ((size_t)nwi * HEADS + h) * LW * LW;
    const float* maskp = mask + (size_t)w * LW * LW;
    float* outp = g_att + (size_t)w * LW * CDIM + h * HD;

    // ---- fill K [l][d] and Vt [d][l] (g_v already transposed -> contiguous STS.128) ----
    for (int idx = tid; idx < LW * HD / 4; idx += 288) {
        int l = idx >> 3, dc = (idx & 7) << 2;
        float4 kk4 = *(const float4*)(g_k + base + (size_t)idx * 4);
        *(float4*)&Ks[l * 36 + dc] = tf32r4(kk4);
        int d = idx / 36, lc = (idx % 36) * 4;
        float4 vv4 = *(const float4*)(g_v + base + (size_t)idx * 4);
        *(float4*)&Vt[d * 148 + lc] = tf32r4(vv4);
    }
    // ---- Q chunk 0 ----
    for (int idx = tid; idx < 48 * HD / 4; idx += 288) {
        int l = idx >> 3, dc = (idx & 7) << 2;
        float4 q4 = *(const float4*)(g_q + base + (size_t)idx * 4);
        *(float4*)&Qs[l * 36 + dc] = tf32r4(q4);
    }
    __syncthreads();

    // ---- pinned K-fragments (this warp's n16 columns) ----
    const int n0 = wid * 16;
    unsigned bq[4][4];
    {
        int brow = n0 + (lane & 7) + ((lane & 16) ? 8 : 0);
#pragma unroll
        for (int kk = 0; kk < 4; kk++) {
            int bcol = kk * 8 + ((lane & 8) ? 4 : 0);
            ldsm4(bq[kk][0], bq[kk][1], bq[kk][2], bq[kk][3], sptr(Ks + brow * 36 + bcol));
        }
    }

#pragma unroll 1
    for (int c = 0; c < 3; c++) {
        const int cbase = c * 48;

        // --- QK: S(local) = Q Kt; 3 m-tiles, warp owns n16 ---
#pragma unroll
        for (int mt = 0; mt < 3; mt++) {
            int m0 = mt * 16;
            unsigned aq[4][4];
            int arow = m0 + (lane & 15);
#pragma unroll
            for (int kk = 0; kk < 4; kk++) {
                int acol = kk * 8 + ((lane & 16) ? 4 : 0);
                ldsm4(aq[kk][0], aq[kk][1], aq[kk][2], aq[kk][3], sptr(Qs + arow * 36 + acol));
            }
            float acc[2][4];
#pragma unroll
            for (int ni = 0; ni < 2; ni++)
#pragma unroll
                for (int r = 0; r < 4; r++) acc[ni][r] = 0.f;
#pragma unroll
            for (int kk = 0; kk < 4; kk++)
#pragma unroll
                for (int ni = 0; ni < 2; ni++)
                    mma8(acc[ni], aq[kk][0], aq[kk][1], aq[kk][2], aq[kk][3],
                         bq[kk][ni * 2], bq[kk][ni * 2 + 1]);
#pragma unroll
            for (int ni = 0; ni < 2; ni++)
#pragma unroll
                for (int r2 = 0; r2 < 2; r2++) {
                    int ll = m0 + g + r2 * 8;
                    int mc = n0 + ni * 8 + tg * 2;
                    *(float2*)&Ss[ll * 148 + mc] =
                        make_float2(acc[ni][r2 * 2], acc[ni][r2 * 2 + 1]);
                }
        }
        __syncthreads();

        // --- prefetch next Q chunk (Qs free now) ---
        if (c < 2) {
            for (int idx = tid; idx < 48 * HD / 4; idx += 288) {
                int l = idx >> 3, dc = (idx & 7) << 2;
                float4 q4 = *(const float4*)(g_q + base + (size_t)((cbase + 48) * HD)
                                             + (size_t)idx * 4);
                *(float4*)&Qs[l * 36 + dc] = tf32r4(q4);
            }
        }

        // --- softmax over rows (bias + mask added here, coalesced) ---
        for (int l = wid; l < 48; l += 9) {
            const int lg = cbase + l;
            const float* bro = biasp + (size_t)lg * LW;
            const float* mro = maskp + (size_t)lg * LW;
            float vb[5];
            float mx = -1e30f;
#pragma unroll
            for (int i = 0; i < 5; i++) {
                int cc = lane + 32 * i;
                vb[i] = (cc < LW) ? (Ss[l * 148 + cc] + bro[cc] + mro[cc]) : -1e30f;
                mx = fmaxf(mx, vb[i]);
            }
#pragma unroll
            for (int o = 16; o; o >>= 1) mx = fmaxf(mx, __shfl_xor_sync(0xffffffffu, mx, o));
            float s = 0.f;
#pragma unroll
            for (int i = 0; i < 5; i++) {
                int cc = lane + 32 * i;
                float e = (cc < LW) ? __expf(vb[i] - mx) : 0.f;
                vb[i] = e; s += e;
            }
#pragma unroll
            for (int o = 16; o; o >>= 1) s += __shfl_xor_sync(0xffffffffu, s, o);
            float inv = 1.f / s;
#pragma unroll
            for (int i = 0; i < 5; i++) {
                int cc = lane + 32 * i;
                if (cc < LW) Ss[l * 148 + cc] = tf32r(vb[i] * inv);
            }
        }
        __syncthreads();

        // --- PV: 12 jobs (3 m-tiles x 4 n8) ---
        for (int job = wid; job < 12; job += 9) {
            int mt = job >> 2;
            int d0 = (job & 3) * 8;
            float acc[4] = {0.f, 0.f, 0.f, 0.f};
            int arow = mt * 16 + (lane & 15);
            int acolo = (lane & 16) ? 4 : 0;
            int vrow = d0 + (lane & 7);
            int vcolo = (lane & 8) ? 4 : 0;
#pragma unroll
            for (int ks = 0; ks < 18; ks++) {
                int kb = ks * 8;
                unsigned a0, a1, a2, a3, b0, b1;
                ldsm4(a0, a1, a2, a3, sptr(Ss + arow * 148 + kb + acolo));
                ldsm2(b0, b1, sptr(Vt + vrow * 148 + kb + vcolo));
                mma8(acc, a0, a1, a2, a3, b0, b1);
            }
#pragma unroll
            for (int r2 = 0; r2 < 2; r2++) {
                int lg = cbase + mt * 16 + g + r2 * 8;
                int d = d0 + tg * 2;
                *(float2*)(outp + (size_t)lg * CDIM + d) =
                    make_float2(acc[r2 * 2], acc[r2 * 2 + 1]);
            }
        }
        __syncthreads();
    }
}

// ---------------- kernel 3: out-projection GEMM ----------------
__global__ __launch_bounds__(256) void k_proj(const float* __restrict__ W2,
                                              const float* __restrict__ b2,
                                              float* __restrict__ out) {
    __shared__ __align__(16) float As[2][128][36];
    __shared__ __align__(16) float Bs[2][32][72];

    const int tid  = threadIdx.x;
    const int lane = tid & 31, wid = tid >> 5;
    const int g = lane >> 2, tg = lane & 3;
    const int wm = wid >> 1, wn = wid & 1;
    const int mblk = blockIdx.y * 128;
    const int nblk = blockIdx.x * 64;

    float4 ra[4], rb[2];
#pragma unroll
    for (int i = 0; i < 4; i++) {
        int idx = tid + 256 * i; int r = idx >> 3, kc = (idx & 7) << 2;
        ra[i] = *(const float4*)(g_att + (size_t)(mblk + r) * CDIM + kc);
    }
#pragma unroll
    for (int i = 0; i < 2; i++) {
        int idx = tid + 256 * i; int kr = idx >> 4, nc = (idx & 15) << 2;
        rb[i] = *(const float4*)(W2 + (size_t)kr * CDIM + nblk + nc);
    }
#pragma unroll
    for (int i = 0; i < 4; i++) {
        int idx = tid + 256 * i; int r = idx >> 3, kc = (idx & 7) << 2;
        *(float4*)&As[0][r][kc] = tf32r4(ra[i]);
    }
#pragma unroll
    for (int i = 0; i < 2; i++) {
        int idx = tid + 256 * i; int kr = idx >> 4, nc = (idx & 15) << 2;
        *(float4*)&Bs[0][kr][nc] = tf32r4(rb[i]);
    }
    __syncthreads();

    float acc[2][4][4];
#pragma unroll
    for (int i = 0; i < 2; i++)
#pragma unroll
        for (int j = 0; j < 4; j++)
#pragma unroll
            for (int r = 0; r < 4; r++) acc[i][j][r] = 0.f;

    for (int kt = 0; kt < 6; kt++) {
        const int cur = kt & 1;
        if (kt < 5) {
            const int k0 = (kt + 1) * 32;
#pragma unroll
            for (int i = 0; i < 4; i++) {
                int idx = tid + 256 * i; int r = idx >> 3, kc = (idx & 7) << 2;
                ra[i] = *(const float4*)(g_att + (size_t)(mblk + r) * CDIM + k0 + kc);
            }
#pragma unroll
            for (int i = 0; i < 2; i++) {
                int idx = tid + 256 * i; int kr = idx >> 4, nc = (idx & 15) << 2;
                rb[i] = *(const float4*)(W2 + (size_t)(k0 + kr) * CDIM + nblk + nc);
            }
        }
#pragma unroll
        for (int kk = 0; kk < 4; kk++) {
            const int kb = kk * 8;
            unsigned a[2][4], b[4][2];
#pragma unroll
            for (int mi = 0; mi < 2; mi++) {
                int arow = wm * 32 + mi * 16 + (lane & 15);
                int acol = kb + ((lane & 16) ? 4 : 0);
                ldsm4(a[mi][0], a[mi][1], a[mi][2], a[mi][3], sptr(&As[cur][arow][acol]));
            }
#pragma unroll
            for (int ni = 0; ni < 4; ni++) {
                int c0 = wn * 32 + ni * 8;
                b[ni][0] = __float_as_uint(Bs[cur][kb + tg][c0 + g]);
                b[ni][1] = __float_as_uint(Bs[cur][kb + tg + 4][c0 + g]);
            }
#pragma unroll
            for (int mi = 0; mi < 2; mi++)
#pragma unroll
                for (int ni = 0; ni < 4; ni++)
                    mma8(acc[mi][ni], a[mi][0], a[mi][1], a[mi][2], a[mi][3],
                         b[ni][0], b[ni][1]);
        }
        if (kt < 5) {
            const int nxt = cur ^ 1;
#pragma unroll
            for (int i = 0; i < 4; i++) {
                int idx = tid + 256 * i; int r = idx >> 3, kc = (idx & 7) << 2;
                *(float4*)&As[nxt][r][kc] = tf32r4(ra[i]);
            }
#pragma unroll
            for (int i = 0; i < 2; i++) {
                int idx = tid + 256 * i; int kr = idx >> 4, nc = (idx & 15) << 2;
                *(float4*)&Bs[nxt][kr][nc] = tf32r4(rb[i]);
            }
        }
        __syncthreads();
    }

#pragma unroll
    for (int mi = 0; mi < 2; mi++)
#pragma unroll
        for (int ni = 0; ni < 4; ni++)
#pragma unroll
            for (int r2 = 0; r2 < 2; r2++) {
                int mrow = mblk + wm * 32 + mi * 16 + g + r2 * 8;
                int n    = nblk + wn * 32 + ni * 8 + tg * 2;
                float v0 = acc[mi][ni][r2 * 2 + 0] + b2[n];
                float v1 = acc[mi][ni][r2 * 2 + 1] + b2[n + 1];
                *(float2*)(out + (size_t)mrow * CDIM + n) = make_float2(v0, v1);
            }
}

// ---------------- launch ----------------
extern "C" void kernel_launch(void* const* d_in, const int* in_sizes, int n_in,
                              void* d_out, int out_size) {
    const float* x     = (const float*)d_in[0];
    const float* mask  = (const float*)d_in[1];
    const float* W1    = (const float*)d_in[2];
    const float* b1    = (const float*)d_in[3];
    const float* W2    = (const float*)d_in[4];
    const float* b2    = (const float*)d_in[5];
    const float* table = (const float*)d_in[6];
    const int*   pidx  = (const int*)d_in[7];

    cudaFuncSetAttribute(k_attn, cudaFuncAttributeMaxDynamicSharedMemorySize, SMEM_ATT);

    k_bias<<<(NW * HEADS * LW * LW + 255) / 256, 256>>>(table, pidx);
    k_qkv<<<dim3(N1 / 64, M1 / 128), 256>>>(x, W1, b1);
    k_attn<<<dim3(HEADS, BTOT), 288, SMEM_ATT>>>(mask);
    k_proj<<<dim3(CDIM / 64, M1 / 128), 256>>>(W2, b2, (float*)d_out);
}

// round 4
// speedup vs baseline: 1.4749x; 1.0207x over previous
#include <cuda_runtime.h>
#include <cstdint>

// ---------------- problem constants (static shapes) ----------------
#define HEADS 6
#define LW    144
#define HD    32
#define CDIM  192
#define NW    64
#define WWINS 15
#define BTOT  960
#define M1    (BTOT*LW)      // 138240
#define N1    576
#define K1    192
#define TABNH (NW*HEADS)

// ---------------- scratch (device globals; no allocations) ----------------
__device__ float g_q[(size_t)BTOT*HEADS*LW*HD];
__device__ float g_k[(size_t)BTOT*HEADS*LW*HD];
__device__ float g_v[(size_t)BTOT*HEADS*LW*HD];   // stored TRANSPOSED: [w][h][d][l]
__device__ float g_bias[(size_t)NW*HEADS*LW*LW];
__device__ float g_att[(size_t)BTOT*LW*CDIM];

// ---------------- helpers ----------------
__device__ __forceinline__ float tf32r(float x) {
    unsigned int u;
    asm("cvt.rna.tf32.f32 %0, %1;" : "=r"(u) : "f"(x));
    return __uint_as_float(u);
}

__device__ __forceinline__ float4 tf32r4(float4 v) {
    float4 t;
    t.x = tf32r(v.x); t.y = tf32r(v.y); t.z = tf32r(v.z); t.w = tf32r(v.w);
    return t;
}

__device__ __forceinline__ void mma8(float c[4],
                                     unsigned a0, unsigned a1, unsigned a2, unsigned a3,
                                     unsigned b0, unsigned b1) {
    asm volatile(
        "mma.sync.aligned.m16n8k8.row.col.f32.tf32.tf32.f32 "
        "{%0,%1,%2,%3}, {%4,%5,%6,%7}, {%8,%9}, {%0,%1,%2,%3};\n"
        : "+f"(c[0]), "+f"(c[1]), "+f"(c[2]), "+f"(c[3])
        : "r"(a0), "r"(a1), "r"(a2), "r"(a3), "r"(b0), "r"(b1));
}

__device__ __forceinline__ uint32_t sptr(const float* p) {
    return (uint32_t)__cvta_generic_to_shared(p);
}

__device__ __forceinline__ void ldsm4(unsigned& r0, unsigned& r1, unsigned& r2, unsigned& r3,
                                      uint32_t a) {
    asm volatile("ldmatrix.sync.aligned.m8n8.x4.shared.b16 {%0,%1,%2,%3}, [%4];\n"
                 : "=r"(r0), "=r"(r1), "=r"(r2), "=r"(r3) : "r"(a));
}

__device__ __forceinline__ void ldsm2(unsigned& r0, unsigned& r1, uint32_t a) {
    asm volatile("ldmatrix.sync.aligned.m8n8.x2.shared.b16 {%0,%1}, [%2];\n"
                 : "=r"(r0), "=r"(r1) : "r"(a));
}

// ---------------- kernel 0: expand bias table ----------------
__global__ __launch_bounds__(256) void k_bias(const float* __restrict__ table,
                                              const int* __restrict__ pidx) {
    int idx = blockIdx.x * 256 + threadIdx.x;
    if (idx >= NW * HEADS * LW * LW) return;
    int m  = idx % LW;
    int l  = (idx / LW) % LW;
    int h  = (idx / (LW * LW)) % HEADS;
    int nw = idx / (LW * LW * HEADS);
    g_bias[idx] = table[(size_t)pidx[l * LW + m] * TABNH + nw * HEADS + h];
}

// ============= big-tile GEMM core: block 128x192, 384 thr, warp m32 x n64 =============
// dynamic smem: As[2][128][36] + Bs[2][32][200]
#define GEMM_SMEM ((2*128*36 + 2*32*200) * 4)

// ---------------- kernel 1: QKV = x @ W1 + b1 (scatter epilogue) ----------------
__global__ __launch_bounds__(384) void k_qkv(const float* __restrict__ x,
                                             const float* __restrict__ W1,
                                             const float* __restrict__ b1) {
    extern __shared__ __align__(16) float smg[];
    float* As = smg;                   // [2][128][36]
    float* Bs = smg + 2 * 128 * 36;    // [2][32][200]

    const int tid  = threadIdx.x;
    const int lane = tid & 31, wid = tid >> 5;
    const int g = lane >> 2, tg = lane & 3;
    const int wm = wid & 3, wn = wid >> 2;          // 4 x 3 warps
    const int mblk = blockIdx.y * 128;
    const int nblk = blockIdx.x * 192;

    float4 ra[3], rb[4];
#pragma unroll
    for (int i = 0; i < 3; i++) {
        int idx = tid + 384 * i;
        if (idx < 1024) {
            int r = idx >> 3, kc = (idx & 7) << 2;
            ra[i] = *(const float4*)(x + (size_t)(mblk + r) * K1 + kc);
        }
    }
#pragma unroll
    for (int i = 0; i < 4; i++) {
        int idx = tid + 384 * i;
        int kr = idx / 48, nc = (idx % 48) << 2;
        rb[i] = *(const float4*)(W1 + (size_t)kr * N1 + nblk + nc);
    }
#pragma unroll
    for (int i = 0; i < 3; i++) {
        int idx = tid + 384 * i;
        if (idx < 1024) {
            int r = idx >> 3, kc = (idx & 7) << 2;
            *(float4*)&As[(size_t)r * 36 + kc] = tf32r4(ra[i]);
        }
    }
#pragma unroll
    for (int i = 0; i < 4; i++) {
        int idx = tid + 384 * i;
        int kr = idx / 48, nc = (idx % 48) << 2;
        *(float4*)&Bs[(size_t)kr * 200 + nc] = tf32r4(rb[i]);
    }
    __syncthreads();

    float acc[2][8][4];
#pragma unroll
    for (int i = 0; i < 2; i++)
#pragma unroll
        for (int j = 0; j < 8; j++)
#pragma unroll
            for (int r = 0; r < 4; r++) acc[i][j][r] = 0.f;

    for (int kt = 0; kt < 6; kt++) {
        const int cur = kt & 1;
        float* Ac = As + (size_t)cur * (128 * 36);
        float* Bc = Bs + (size_t)cur * (32 * 200);
        if (kt < 5) {
            const int k0 = (kt + 1) * 32;
#pragma unroll
            for (int i = 0; i < 3; i++) {
                int idx = tid + 384 * i;
                if (idx < 1024) {
                    int r = idx >> 3, kc = (idx & 7) << 2;
                    ra[i] = *(const float4*)(x + (size_t)(mblk + r) * K1 + k0 + kc);
                }
            }
#pragma unroll
            for (int i = 0; i < 4; i++) {
                int idx = tid + 384 * i;
                int kr = idx / 48, nc = (idx % 48) << 2;
                rb[i] = *(const float4*)(W1 + (size_t)(k0 + kr) * N1 + nblk + nc);
            }
        }
#pragma unroll
        for (int kk = 0; kk < 4; kk++) {
            const int kb = kk * 8;
            unsigned a[2][4];
#pragma unroll
            for (int mi = 0; mi < 2; mi++) {
                int arow = wm * 32 + mi * 16 + (lane & 15);
                int acol = kb + ((lane & 16) ? 4 : 0);
                ldsm4(a[mi][0], a[mi][1], a[mi][2], a[mi][3], sptr(Ac + arow * 36 + acol));
            }
#pragma unroll
            for (int ni = 0; ni < 8; ni++) {
                int c0 = wn * 64 + ni * 8;
                unsigned b0 = __float_as_uint(Bc[(kb + tg) * 200 + c0 + g]);
                unsigned b1 = __float_as_uint(Bc[(kb + tg + 4) * 200 + c0 + g]);
#pragma unroll
                for (int mi = 0; mi < 2; mi++)
                    mma8(acc[mi][ni], a[mi][0], a[mi][1], a[mi][2], a[mi][3], b0, b1);
            }
        }
        if (kt < 5) {
            float* An = As + (size_t)(cur ^ 1) * (128 * 36);
            float* Bn = Bs + (size_t)(cur ^ 1) * (32 * 200);
#pragma unroll
            for (int i = 0; i < 3; i++) {
                int idx = tid + 384 * i;
                if (idx < 1024) {
                    int r = idx >> 3, kc = (idx & 7) << 2;
                    *(float4*)&An[(size_t)r * 36 + kc] = tf32r4(ra[i]);
                }
            }
#pragma unroll
            for (int i = 0; i < 4; i++) {
                int idx = tid + 384 * i;
                int kr = idx / 48, nc = (idx % 48) << 2;
                *(float4*)&Bn[(size_t)kr * 200 + nc] = tf32r4(rb[i]);
            }
        }
        __syncthreads();
    }

    const float SCALE = 0.17677669529663687f;
#pragma unroll
    for (int mi = 0; mi < 2; mi++)
#pragma unroll
        for (int ni = 0; ni < 8; ni++)
#pragma unroll
            for (int r2 = 0; r2 < 2; r2++) {
                int mrow = mblk + wm * 32 + mi * 16 + g + r2 * 8;
                int n    = nblk + wn * 64 + ni * 8 + tg * 2;
                float v0 = acc[mi][ni][r2 * 2 + 0] + b1[n];
                float v1 = acc[mi][ni][r2 * 2 + 1] + b1[n + 1];
                int which = n / 192;
                int nm    = n % 192;
                int head  = nm / 32;
                int d     = nm & 31;
                int win   = mrow / LW;
                int l     = mrow - win * LW;
                if (which == 0) {
                    size_t dst = (((size_t)win * HEADS + head) * LW + l) * HD + d;
                    *(float2*)(g_q + dst) = make_float2(v0 * SCALE, v1 * SCALE);
                } else if (which == 1) {
                    size_t dst = (((size_t)win * HEADS + head) * LW + l) * HD + d;
                    *(float2*)(g_k + dst) = make_float2(v0, v1);
                } else {
                    size_t baset = ((size_t)win * HEADS + head) * (size_t)(HD * LW);
                    g_v[baset + (size_t)d * LW + l]       = v0;
                    g_v[baset + (size_t)(d + 1) * LW + l] = v1;
                }
            }
}

// ---------------- kernel 2: fused attention, 9 warps, 3 chunks of 48 rows ----------------
// smem: Ks[144][36] | Vt[32][148] | Qs[48][36] | Ss[48][148] = 73.25 KB -> 3 blocks/SM
#define SMEM_ATT ((LW*36 + HD*148 + 48*36 + 48*148) * 4)

__global__ __launch_bounds__(288, 3) void k_attn(const float* __restrict__ mask) {
    extern __shared__ __align__(16) float sm[];
    float* Ks = sm;                  // [144][36]
    float* Vt = Ks + LW * 36;        // [32][148]
    float* Qs = Vt + HD * 148;       // [48][36]
    float* Ss = Qs + 48 * 36;        // [48][148]

    const int h = blockIdx.x;
    const int w = blockIdx.y;
    const int nwi = w / WWINS;
    const int tid = threadIdx.x, lane = tid & 31, wid = tid >> 5;   // wid 0..8
    const int g = lane >> 2, tg = lane & 3;

    const size_t base = ((size_t)w * HEADS + h) * LW * HD;
    const float* biasp = g_bias + ((size_t)nwi * HEADS + h) * LW * LW;
    const float* maskp = mask + (size_t)w * LW * LW;
    float* outp = g_att + (size_t)w * LW * CDIM + h * HD;

    // ---- fill K [l][d] and Vt [d][l] ----
    for (int idx = tid; idx < LW * HD / 4; idx += 288) {
        int l = idx >> 3, dc = (idx & 7) << 2;
        float4 kk4 = *(const float4*)(g_k + base + (size_t)idx * 4);
        *(float4*)&Ks[l * 36 + dc] = tf32r4(kk4);
        int d = idx / 36, lc = (idx % 36) * 4;
        float4 vv4 = *(const float4*)(g_v + base + (size_t)idx * 4);
        *(float4*)&Vt[d * 148 + lc] = tf32r4(vv4);
    }
    // ---- Q chunk 0 ----
    for (int idx = tid; idx < 48 * HD / 4; idx += 288) {
        int l = idx >> 3, dc = (idx & 7) << 2;
        float4 q4 = *(const float4*)(g_q + base + (size_t)idx * 4);
        *(float4*)&Qs[l * 36 + dc] = tf32r4(q4);
    }
    __syncthreads();

    // ---- pinned K-fragments (this warp's n16 columns) ----
    const int n0 = wid * 16;
    unsigned bq[4][4];
    {
        int brow = n0 + (lane & 7) + ((lane & 16) ? 8 : 0);
#pragma unroll
        for (int kk = 0; kk < 4; kk++) {
            int bcol = kk * 8 + ((lane & 8) ? 4 : 0);
            ldsm4(bq[kk][0], bq[kk][1], bq[kk][2], bq[kk][3], sptr(Ks + brow * 36 + bcol));
        }
    }

    // PV job decomposition: 9 jobs for 9 warps.
    const int pv_mt   = wid / 3;           // 0..2
    const int pv_slot = wid % 3;           // 0: d[0,8) 1: d[8,16) 2: d[16,32)

#pragma unroll 1
    for (int c = 0; c < 3; c++) {
        const int cbase = c * 48;

        // --- QK ---
#pragma unroll
        for (int mt = 0; mt < 3; mt++) {
            int m0 = mt * 16;
            unsigned aq[4][4];
            int arow = m0 + (lane & 15);
#pragma unroll
            for (int kk = 0; kk < 4; kk++) {
                int acol = kk * 8 + ((lane & 16) ? 4 : 0);
                ldsm4(aq[kk][0], aq[kk][1], aq[kk][2], aq[kk][3], sptr(Qs + arow * 36 + acol));
            }
            float acc[2][4];
#pragma unroll
            for (int ni = 0; ni < 2; ni++)
#pragma unroll
                for (int r = 0; r < 4; r++) acc[ni][r] = 0.f;
#pragma unroll
            for (int kk = 0; kk < 4; kk++)
#pragma unroll
                for (int ni = 0; ni < 2; ni++)
                    mma8(acc[ni], aq[kk][0], aq[kk][1], aq[kk][2], aq[kk][3],
                         bq[kk][ni * 2], bq[kk][ni * 2 + 1]);
#pragma unroll
            for (int ni = 0; ni < 2; ni++)
#pragma unroll
                for (int r2 = 0; r2 < 2; r2++) {
                    int ll = m0 + g + r2 * 8;
                    int mc = n0 + ni * 8 + tg * 2;
                    *(float2*)&Ss[ll * 148 + mc] =
                        make_float2(acc[ni][r2 * 2], acc[ni][r2 * 2 + 1]);
                }
        }
        __syncthreads();

        // --- prefetch next Q chunk ---
        if (c < 2) {
            for (int idx = tid; idx < 48 * HD / 4; idx += 288) {
                int l = idx >> 3, dc = (idx & 7) << 2;
                float4 q4 = *(const float4*)(g_q + base + (size_t)((cbase + 48) * HD)
                                             + (size_t)idx * 4);
                *(float4*)&Qs[l * 36 + dc] = tf32r4(q4);
            }
        }

        // --- softmax (bias + mask fused, coalesced) ---
        for (int l = wid; l < 48; l += 9) {
            const int lg = cbase + l;
            const float* bro = biasp + (size_t)lg * LW;
            const float* mro = maskp + (size_t)lg * LW;
            float vb[5];
            float mx = -1e30f;
#pragma unroll
            for (int i = 0; i < 5; i++) {
                int cc = lane + 32 * i;
                vb[i] = (cc < LW) ? (Ss[l * 148 + cc] + bro[cc] + mro[cc]) : -1e30f;
                mx = fmaxf(mx, vb[i]);
            }
#pragma unroll
            for (int o = 16; o; o >>= 1) mx = fmaxf(mx, __shfl_xor_sync(0xffffffffu, mx, o));
            float s = 0.f;
#pragma unroll
            for (int i = 0; i < 5; i++) {
                int cc = lane + 32 * i;
                float e = (cc < LW) ? __expf(vb[i] - mx) : 0.f;
                vb[i] = e; s += e;
            }
#pragma unroll
            for (int o = 16; o; o >>= 1) s += __shfl_xor_sync(0xffffffffu, s, o);
            float inv = 1.f / s;
#pragma unroll
            for (int i = 0; i < 5; i++) {
                int cc = lane + 32 * i;
                if (cc < LW) Ss[l * 148 + cc] = tf32r(vb[i] * inv);
            }
        }
        __syncthreads();

        // --- PV: one job per warp ---
        {
            const int m0 = pv_mt * 16;
            const int arow = m0 + (lane & 15);
            const int acolo = (lane & 16) ? 4 : 0;
            if (pv_slot < 2) {
                const int d0 = pv_slot * 8;
                float acc[4] = {0.f, 0.f, 0.f, 0.f};
                int vrow = d0 + (lane & 7);
                int vcolo = (lane & 8) ? 4 : 0;
#pragma unroll
                for (int ks = 0; ks < 18; ks++) {
                    int kb = ks * 8;
                    unsigned a0, a1, a2, a3, b0, b1;
                    ldsm4(a0, a1, a2, a3, sptr(Ss + arow * 148 + kb + acolo));
                    ldsm2(b0, b1, sptr(Vt + vrow * 148 + kb + vcolo));
                    mma8(acc, a0, a1, a2, a3, b0, b1);
                }
#pragma unroll
                for (int r2 = 0; r2 < 2; r2++) {
                    int lg = cbase + m0 + g + r2 * 8;
                    int d = d0 + tg * 2;
                    *(float2*)(outp + (size_t)lg * CDIM + d) =
                        make_float2(acc[r2 * 2], acc[r2 * 2 + 1]);
                }
            } else {
                // n16 job: d in [16,32)
                float acc[2][4];
#pragma unroll
                for (int ni = 0; ni < 2; ni++)
#pragma unroll
                    for (int r = 0; r < 4; r++) acc[ni][r] = 0.f;
                int vrow = 16 + (lane & 7) + ((lane & 16) ? 8 : 0);
                int vcolo = (lane & 8) ? 4 : 0;
#pragma unroll
                for (int ks = 0; ks < 18; ks++) {
                    int kb = ks * 8;
                    unsigned a0, a1, a2, a3, b0, b1, b2, b3;
                    ldsm4(a0, a1, a2, a3, sptr(Ss + arow * 148 + kb + acolo));
                    ldsm4(b0, b1, b2, b3, sptr(Vt + vrow * 148 + kb + vcolo));
                    mma8(acc[0], a0, a1, a2, a3, b0, b1);
                    mma8(acc[1], a0, a1, a2, a3, b2, b3);
                }
#pragma unroll
                for (int ni = 0; ni < 2; ni++)
#pragma unroll
                    for (int r2 = 0; r2 < 2; r2++) {
                        int lg = cbase + m0 + g + r2 * 8;
                        int d = 16 + ni * 8 + tg * 2;
                        *(float2*)(outp + (size_t)lg * CDIM + d) =
                            make_float2(acc[ni][r2 * 2], acc[ni][r2 * 2 + 1]);
                    }
            }
        }
        __syncthreads();
    }
}

// ---------------- kernel 3: out = att @ W2 + b2 ----------------
__global__ __launch_bounds__(384) void k_proj(const float* __restrict__ W2,
                                              const float* __restrict__ b2,
                                              float* __restrict__ out) {
    extern __shared__ __align__(16) float smg[];
    float* As = smg;
    float* Bs = smg + 2 * 128 * 36;

    const int tid  = threadIdx.x;
    const int lane = tid & 31, wid = tid >> 5;
    const int g = lane >> 2, tg = lane & 3;
    const int wm = wid & 3, wn = wid >> 2;
    const int mblk = blockIdx.x * 128;

    float4 ra[3], rb[4];
#pragma unroll
    for (int i = 0; i < 3; i++) {
        int idx = tid + 384 * i;
        if (idx < 1024) {
            int r = idx >> 3, kc = (idx & 7) << 2;
            ra[i] = *(const float4*)(g_att + (size_t)(mblk + r) * CDIM + kc);
        }
    }
#pragma unroll
    for (int i = 0; i < 4; i++) {
        int idx = tid + 384 * i;
        int kr = idx / 48, nc = (idx % 48) << 2;
        rb[i] = *(const float4*)(W2 + (size_t)kr * CDIM + nc);
    }
#pragma unroll
    for (int i = 0; i < 3; i++) {
        int idx = tid + 384 * i;
        if (idx < 1024) {
            int r = idx >> 3, kc = (idx & 7) << 2;
            *(float4*)&As[(size_t)r * 36 + kc] = tf32r4(ra[i]);
        }
    }
#pragma unroll
    for (int i = 0; i < 4; i++) {
        int idx = tid + 384 * i;
        int kr = idx / 48, nc = (idx % 48) << 2;
        *(float4*)&Bs[(size_t)kr * 200 + nc] = tf32r4(rb[i]);
    }
    __syncthreads();

    float acc[2][8][4];
#pragma unroll
    for (int i = 0; i < 2; i++)
#pragma unroll
        for (int j = 0; j < 8; j++)
#pragma unroll
            for (int r = 0; r < 4; r++) acc[i][j][r] = 0.f;

    for (int kt = 0; kt < 6; kt++) {
        const int cur = kt & 1;
        float* Ac = As + (size_t)cur * (128 * 36);
        float* Bc = Bs + (size_t)cur * (32 * 200);
        if (kt < 5) {
            const int k0 = (kt + 1) * 32;
#pragma unroll
            for (int i = 0; i < 3; i++) {
                int idx = tid + 384 * i;
                if (idx < 1024) {
                    int r = idx >> 3, kc = (idx & 7) << 2;
                    ra[i] = *(const float4*)(g_att + (size_t)(mblk + r) * CDIM + k0 + kc);
                }
            }
#pragma unroll
            for (int i = 0; i < 4; i++) {
                int idx = tid + 384 * i;
                int kr = idx / 48, nc = (idx % 48) << 2;
                rb[i] = *(const float4*)(W2 + (size_t)(k0 + kr) * CDIM + nc);
            }
        }
#pragma unroll
        for (int kk = 0; kk < 4; kk++) {
            const int kb = kk * 8;
            unsigned a[2][4];
#pragma unroll
            for (int mi = 0; mi < 2; mi++) {
                int arow = wm * 32 + mi * 16 + (lane & 15);
                int acol = kb + ((lane & 16) ? 4 : 0);
                ldsm4(a[mi][0], a[mi][1], a[mi][2], a[mi][3], sptr(Ac + arow * 36 + acol));
            }
#pragma unroll
            for (int ni = 0; ni < 8; ni++) {
                int c0 = wn * 64 + ni * 8;
                unsigned b0 = __float_as_uint(Bc[(kb + tg) * 200 + c0 + g]);
                unsigned b1 = __float_as_uint(Bc[(kb + tg + 4) * 200 + c0 + g]);
#pragma unroll
                for (int mi = 0; mi < 2; mi++)
                    mma8(acc[mi][ni], a[mi][0], a[mi][1], a[mi][2], a[mi][3], b0, b1);
            }
        }
        if (kt < 5) {
            float* An = As + (size_t)(cur ^ 1) * (128 * 36);
            float* Bn = Bs + (size_t)(cur ^ 1) * (32 * 200);
#pragma unroll
            for (int i = 0; i < 3; i++) {
                int idx = tid + 384 * i;
                if (idx < 1024) {
                    int r = idx >> 3, kc = (idx & 7) << 2;
                    *(float4*)&An[(size_t)r * 36 + kc] = tf32r4(ra[i]);
                }
            }
#pragma unroll
            for (int i = 0; i < 4; i++) {
                int idx = tid + 384 * i;
                int kr = idx / 48, nc = (idx % 48) << 2;
                *(float4*)&Bn[(size_t)kr * 200 + nc] = tf32r4(rb[i]);
            }
        }
        __syncthreads();
    }

#pragma unroll
    for (int mi = 0; mi < 2; mi++)
#pragma unroll
        for (int ni = 0; ni < 8; ni++)
#pragma unroll
            for (int r2 = 0; r2 < 2; r2++) {
                int mrow = mblk + wm * 32 + mi * 16 + g + r2 * 8;
                int n    = wn * 64 + ni * 8 + tg * 2;
                float v0 = acc[mi][ni][r2 * 2 + 0] + b2[n];
                float v1 = acc[mi][ni][r2 * 2 + 1] + b2[n + 1];
                *(float2*)(out + (size_t)mrow * CDIM + n) = make_float2(v0, v1);
            }
}

// ---------------- launch ----------------
extern "C" void kernel_launch(void* const* d_in, const int* in_sizes, int n_in,
                              void* d_out, int out_size) {
    const float* x     = (const float*)d_in[0];
    const float* mask  = (const float*)d_in[1];
    const float* W1    = (const float*)d_in[2];
    const float* b1    = (const float*)d_in[3];
    const float* W2    = (const float*)d_in[4];
    const float* b2    = (const float*)d_in[5];
    const float* table = (const float*)d_in[6];
    const int*   pidx  = (const int*)d_in[7];

    cudaFuncSetAttribute(k_attn, cudaFuncAttributeMaxDynamicSharedMemorySize, SMEM_ATT);
    cudaFuncSetAttribute(k_qkv,  cudaFuncAttributeMaxDynamicSharedMemorySize, GEMM_SMEM);
    cudaFuncSetAttribute(k_proj, cudaFuncAttributeMaxDynamicSharedMemorySize, GEMM_SMEM);

    k_bias<<<(NW * HEADS * LW * LW + 255) / 256, 256>>>(table, pidx);
    k_qkv<<<dim3(N1 / 192, M1 / 128), 384, GEMM_SMEM>>>(x, W1, b1);
    k_attn<<<dim3(HEADS, BTOT), 288, SMEM_ATT>>>(mask);
    k_proj<<<M1 / 128, 384, GEMM_SMEM>>>(W2, b2, (float*)d_out);
}

// round 5
// speedup vs baseline: 1.7340x; 1.1757x over previous
#include <cuda_runtime.h>
#include <cstdint>

// ---------------- problem constants (static shapes) ----------------
#define HEADS 6
#define LW    144
#define HD    32
#define CDIM  192
#define NW    64
#define WWINS 15
#define BTOT  960
#define M1    (BTOT*LW)      // 138240
#define N1    576
#define K1    192
#define TABNH (NW*HEADS)

// ---------------- scratch (device globals; no allocations) ----------------
__device__ float g_q[(size_t)BTOT*HEADS*LW*HD];
__device__ float g_k[(size_t)BTOT*HEADS*LW*HD];
__device__ float g_v[(size_t)BTOT*HEADS*LW*HD];   // stored TRANSPOSED: [w][h][d][l]
__device__ float g_bias[(size_t)NW*HEADS*LW*LW];
__device__ float g_att[(size_t)BTOT*LW*CDIM];

// ---------------- helpers ----------------
__device__ __forceinline__ float tf32r(float x) {
    unsigned int u;
    asm("cvt.rna.tf32.f32 %0, %1;" : "=r"(u) : "f"(x));
    return __uint_as_float(u);
}

__device__ __forceinline__ float4 tf32r4(float4 v) {
    float4 t;
    t.x = tf32r(v.x); t.y = tf32r(v.y); t.z = tf32r(v.z); t.w = tf32r(v.w);
    return t;
}

__device__ __forceinline__ void mma8(float c[4],
                                     unsigned a0, unsigned a1, unsigned a2, unsigned a3,
                                     unsigned b0, unsigned b1) {
    asm volatile(
        "mma.sync.aligned.m16n8k8.row.col.f32.tf32.tf32.f32 "
        "{%0,%1,%2,%3}, {%4,%5,%6,%7}, {%8,%9}, {%0,%1,%2,%3};\n"
        : "+f"(c[0]), "+f"(c[1]), "+f"(c[2]), "+f"(c[3])
        : "r"(a0), "r"(a1), "r"(a2), "r"(a3), "r"(b0), "r"(b1));
}

__device__ __forceinline__ uint32_t sptr(const float* p) {
    return (uint32_t)__cvta_generic_to_shared(p);
}

__device__ __forceinline__ void ldsm4(unsigned& r0, unsigned& r1, unsigned& r2, unsigned& r3,
                                      uint32_t a) {
    asm volatile("ldmatrix.sync.aligned.m8n8.x4.shared.b16 {%0,%1,%2,%3}, [%4];\n"
                 : "=r"(r0), "=r"(r1), "=r"(r2), "=r"(r3) : "r"(a));
}

__device__ __forceinline__ void ldsm2(unsigned& r0, unsigned& r1, uint32_t a) {
    asm volatile("ldmatrix.sync.aligned.m8n8.x2.shared.b16 {%0,%1}, [%2];\n"
                 : "=r"(r0), "=r"(r1) : "r"(a));
}

// ---------------- kernel 0: expand bias table ----------------
__global__ __launch_bounds__(256) void k_bias(const float* __restrict__ table,
                                              const int* __restrict__ pidx) {
    int idx = blockIdx.x * 256 + threadIdx.x;
    if (idx >= NW * HEADS * LW * LW) return;
    int m  = idx % LW;
    int l  = (idx / LW) % LW;
    int h  = (idx / (LW * LW)) % HEADS;
    int nw = idx / (LW * LW * HEADS);
    g_bias[idx] = table[(size_t)pidx[l * LW + m] * TABNH + nw * HEADS + h];
}

// ============= big-tile GEMM core: block 128x192, 384 thr, warp m32 x n64 =============
#define GEMM_SMEM ((2*128*36 + 2*32*200) * 4)

// ---------------- kernel 1: QKV = x @ W1 + b1 (scatter epilogue) ----------------
__global__ __launch_bounds__(384) void k_qkv(const float* __restrict__ x,
                                             const float* __restrict__ W1,
                                             const float* __restrict__ b1) {
    extern __shared__ __align__(16) float smg[];
    float* As = smg;                   // [2][128][36]
    float* Bs = smg + 2 * 128 * 36;    // [2][32][200]

    const int tid  = threadIdx.x;
    const int lane = tid & 31, wid = tid >> 5;
    const int g = lane >> 2, tg = lane & 3;
    const int wm = wid & 3, wn = wid >> 2;
    const int mblk = blockIdx.y * 128;
    const int nblk = blockIdx.x * 192;

    float4 ra[3], rb[4];
#pragma unroll
    for (int i = 0; i < 3; i++) {
        int idx = tid + 384 * i;
        if (idx < 1024) {
            int r = idx >> 3, kc = (idx & 7) << 2;
            ra[i] = *(const float4*)(x + (size_t)(mblk + r) * K1 + kc);
        }
    }
#pragma unroll
    for (int i = 0; i < 4; i++) {
        int idx = tid + 384 * i;
        int kr = idx / 48, nc = (idx % 48) << 2;
        rb[i] = *(const float4*)(W1 + (size_t)kr * N1 + nblk + nc);
    }
#pragma unroll
    for (int i = 0; i < 3; i++) {
        int idx = tid + 384 * i;
        if (idx < 1024) {
            int r = idx >> 3, kc = (idx & 7) << 2;
            *(float4*)&As[(size_t)r * 36 + kc] = tf32r4(ra[i]);
        }
    }
#pragma unroll
    for (int i = 0; i < 4; i++) {
        int idx = tid + 384 * i;
        int kr = idx / 48, nc = (idx % 48) << 2;
        *(float4*)&Bs[(size_t)kr * 200 + nc] = tf32r4(rb[i]);
    }
    __syncthreads();

    float acc[2][8][4];
#pragma unroll
    for (int i = 0; i < 2; i++)
#pragma unroll
        for (int j = 0; j < 8; j++)
#pragma unroll
            for (int r = 0; r < 4; r++) acc[i][j][r] = 0.f;

    for (int kt = 0; kt < 6; kt++) {
        const int cur = kt & 1;
        float* Ac = As + (size_t)cur * (128 * 36);
        float* Bc = Bs + (size_t)cur * (32 * 200);
        if (kt < 5) {
            const int k0 = (kt + 1) * 32;
#pragma unroll
            for (int i = 0; i < 3; i++) {
                int idx = tid + 384 * i;
                if (idx < 1024) {
                    int r = idx >> 3, kc = (idx & 7) << 2;
                    ra[i] = *(const float4*)(x + (size_t)(mblk + r) * K1 + k0 + kc);
                }
            }
#pragma unroll
            for (int i = 0; i < 4; i++) {
                int idx = tid + 384 * i;
                int kr = idx / 48, nc = (idx % 48) << 2;
                rb[i] = *(const float4*)(W1 + (size_t)(k0 + kr) * N1 + nblk + nc);
            }
        }
#pragma unroll
        for (int kk = 0; kk < 4; kk++) {
            const int kb = kk * 8;
            unsigned a[2][4];
#pragma unroll
            for (int mi = 0; mi < 2; mi++) {
                int arow = wm * 32 + mi * 16 + (lane & 15);
                int acol = kb + ((lane & 16) ? 4 : 0);
                ldsm4(a[mi][0], a[mi][1], a[mi][2], a[mi][3], sptr(Ac + arow * 36 + acol));
            }
#pragma unroll
            for (int ni = 0; ni < 8; ni++) {
                int c0 = wn * 64 + ni * 8;
                unsigned b0 = __float_as_uint(Bc[(kb + tg) * 200 + c0 + g]);
                unsigned b1 = __float_as_uint(Bc[(kb + tg + 4) * 200 + c0 + g]);
#pragma unroll
                for (int mi = 0; mi < 2; mi++)
                    mma8(acc[mi][ni], a[mi][0], a[mi][1], a[mi][2], a[mi][3], b0, b1);
            }
        }
        if (kt < 5) {
            float* An = As + (size_t)(cur ^ 1) * (128 * 36);
            float* Bn = Bs + (size_t)(cur ^ 1) * (32 * 200);
#pragma unroll
            for (int i = 0; i < 3; i++) {
                int idx = tid + 384 * i;
                if (idx < 1024) {
                    int r = idx >> 3, kc = (idx & 7) << 2;
                    *(float4*)&An[(size_t)r * 36 + kc] = tf32r4(ra[i]);
                }
            }
#pragma unroll
            for (int i = 0; i < 4; i++) {
                int idx = tid + 384 * i;
                int kr = idx / 48, nc = (idx % 48) << 2;
                *(float4*)&Bn[(size_t)kr * 200 + nc] = tf32r4(rb[i]);
            }
        }
        __syncthreads();
    }

    const float SCALE = 0.17677669529663687f;
#pragma unroll
    for (int mi = 0; mi < 2; mi++)
#pragma unroll
        for (int ni = 0; ni < 8; ni++)
#pragma unroll
            for (int r2 = 0; r2 < 2; r2++) {
                int mrow = mblk + wm * 32 + mi * 16 + g + r2 * 8;
                int n    = nblk + wn * 64 + ni * 8 + tg * 2;
                float v0 = acc[mi][ni][r2 * 2 + 0] + b1[n];
                float v1 = acc[mi][ni][r2 * 2 + 1] + b1[n + 1];
                int which = n / 192;
                int nm    = n % 192;
                int head  = nm / 32;
                int d     = nm & 31;
                int win   = mrow / LW;
                int l     = mrow - win * LW;
                if (which == 0) {
                    size_t dst = (((size_t)win * HEADS + head) * LW + l) * HD + d;
                    *(float2*)(g_q + dst) = make_float2(v0 * SCALE, v1 * SCALE);
                } else if (which == 1) {
                    size_t dst = (((size_t)win * HEADS + head) * LW + l) * HD + d;
                    *(float2*)(g_k + dst) = make_float2(v0, v1);
                } else {
                    size_t baset = ((size_t)win * HEADS + head) * (size_t)(HD * LW);
                    g_v[baset + (size_t)d * LW + l]       = v0;
                    g_v[baset + (size_t)(d + 1) * LW + l] = v1;
                }
            }
}

// ---------------- kernel 2: FA2-style fused attention ----------------
// warp owns m16 rows; S/P register-resident; online softmax; one __syncthreads.
// smem: Qs[144][36] + Ks[144][36] + Vt[32][148] = 59 KB -> 2 blocks/SM (reg-bound)
#define SMEM_ATT ((LW*36 + LW*36 + HD*148) * 4)

__global__ __launch_bounds__(288, 2) void k_attn(const float* __restrict__ mask) {
    extern __shared__ __align__(16) float sm[];
    float* Qs = sm;                  // [144][36]
    float* Ks = Qs + LW * 36;        // [144][36]
    float* Vt = Ks + LW * 36;        // [32][148]

    const int h = blockIdx.x;
    const int w = blockIdx.y;
    const int nwi = w / WWINS;
    const int tid = threadIdx.x, lane = tid & 31, wid = tid >> 5;   // wid 0..8
    const int g = lane >> 2, tg = lane & 3;

    const size_t base = ((size_t)w * HEADS + h) * LW * HD;
    const float* biasp = g_bias + ((size_t)nwi * HEADS + h) * LW * LW;
    const float* maskp = mask + (size_t)w * LW * LW;
    float* outp = g_att + (size_t)w * LW * CDIM + h * HD;

    // ---- fill Q [l][d], K [l][d], Vt [d][l] ----
    for (int idx = tid; idx < LW * HD / 4; idx += 288) {
        int l = idx >> 3, dc = (idx & 7) << 2;
        float4 q4 = *(const float4*)(g_q + base + (size_t)idx * 4);
        *(float4*)&Qs[l * 36 + dc] = tf32r4(q4);
        float4 k4 = *(const float4*)(g_k + base + (size_t)idx * 4);
        *(float4*)&Ks[l * 36 + dc] = tf32r4(k4);
        int d = idx / 36, lc = (idx % 36) * 4;
        float4 v4 = *(const float4*)(g_v + base + (size_t)idx * 4);
        *(float4*)&Vt[d * 148 + lc] = tf32r4(v4);
    }
    __syncthreads();

    // ---- pin this warp's Q rows (m16) as A-fragments ----
    const int m0 = wid * 16;
    unsigned aq[4][4];
    {
        int arow = m0 + (lane & 15);
#pragma unroll
        for (int kk = 0; kk < 4; kk++) {
            int acol = kk * 8 + ((lane & 16) ? 4 : 0);
            ldsm4(aq[kk][0], aq[kk][1], aq[kk][2], aq[kk][3], sptr(Qs + arow * 36 + acol));
        }
    }

    const int r0 = m0 + g, r1 = r0 + 8;
    float mr0 = -1e30f, mr1 = -1e30f;   // running max (rows r0, r1)
    float lr0 = 0.f,    lr1 = 0.f;      // running sum
    float oacc[4][4];
#pragma unroll
    for (int ni = 0; ni < 4; ni++)
#pragma unroll
        for (int r = 0; r < 4; r++) oacc[ni][r] = 0.f;

    const int srcA = (lane & ~3) | (tg >> 1);        // quad shuffle sources
    const int srcB = srcA + 2;

#pragma unroll
    for (int cb = 0; cb < 2; cb++) {
        const int c0 = cb * 72;

        // --- S = Q K^T over this 72-col block (9 n8 tiles) ---
        float sacc[9][4];
#pragma unroll
        for (int nt = 0; nt < 9; nt++)
#pragma unroll
            for (int r = 0; r < 4; r++) sacc[nt][r] = 0.f;
#pragma unroll
        for (int nt = 0; nt < 9; nt++) {
            const int nrow = c0 + nt * 8 + (lane & 7);
#pragma unroll
            for (int kk = 0; kk < 4; kk++) {
                unsigned b0, b1;
                ldsm2(b0, b1, sptr(Ks + nrow * 36 + kk * 8 + ((lane & 8) ? 4 : 0)));
                mma8(sacc[nt], aq[kk][0], aq[kk][1], aq[kk][2], aq[kk][3], b0, b1);
            }
        }

        // --- add bias + mask (register-level, coalesced float2 per quad) ---
#pragma unroll
        for (int nt = 0; nt < 9; nt++) {
            int c = c0 + nt * 8 + tg * 2;
            float2 b0v = *(const float2*)(biasp + (size_t)r0 * LW + c);
            float2 m0v = *(const float2*)(maskp + (size_t)r0 * LW + c);
            float2 b1v = *(const float2*)(biasp + (size_t)r1 * LW + c);
            float2 m1v = *(const float2*)(maskp + (size_t)r1 * LW + c);
            sacc[nt][0] += b0v.x + m0v.x;
            sacc[nt][1] += b0v.y + m0v.y;
            sacc[nt][2] += b1v.x + m1v.x;
            sacc[nt][3] += b1v.y + m1v.y;
        }

        // --- online softmax (register + quad shuffles) ---
        float mx0 = -1e30f, mx1 = -1e30f;
#pragma unroll
        for (int nt = 0; nt < 9; nt++) {
            mx0 = fmaxf(mx0, fmaxf(sacc[nt][0], sacc[nt][1]));
            mx1 = fmaxf(mx1, fmaxf(sacc[nt][2], sacc[nt][3]));
        }
        mx0 = fmaxf(mx0, __shfl_xor_sync(0xffffffffu, mx0, 1));
        mx0 = fmaxf(mx0, __shfl_xor_sync(0xffffffffu, mx0, 2));
        mx1 = fmaxf(mx1, __shfl_xor_sync(0xffffffffu, mx1, 1));
        mx1 = fmaxf(mx1, __shfl_xor_sync(0xffffffffu, mx1, 2));
        const float mn0 = fmaxf(mr0, mx0);
        const float mn1 = fmaxf(mr1, mx1);
        const float sc0 = __expf(mr0 - mn0);
        const float sc1 = __expf(mr1 - mn1);
        mr0 = mn0; mr1 = mn1;

        float sum0 = 0.f, sum1 = 0.f;
#pragma unroll
        for (int nt = 0; nt < 9; nt++) {
            sacc[nt][0] = __expf(sacc[nt][0] - mn0);
            sacc[nt][1] = __expf(sacc[nt][1] - mn0);
            sacc[nt][2] = __expf(sacc[nt][2] - mn1);
            sacc[nt][3] = __expf(sacc[nt][3] - mn1);
            sum0 += sacc[nt][0] + sacc[nt][1];
            sum1 += sacc[nt][2] + sacc[nt][3];
        }
        sum0 += __shfl_xor_sync(0xffffffffu, sum0, 1);
        sum0 += __shfl_xor_sync(0xffffffffu, sum0, 2);
        sum1 += __shfl_xor_sync(0xffffffffu, sum1, 1);
        sum1 += __shfl_xor_sync(0xffffffffu, sum1, 2);
        lr0 = lr0 * sc0 + sum0;
        lr1 = lr1 * sc1 + sum1;

        // rescale O accumulator
#pragma unroll
        for (int ni = 0; ni < 4; ni++) {
            oacc[ni][0] *= sc0; oacc[ni][1] *= sc0;
            oacc[ni][2] *= sc1; oacc[ni][3] *= sc1;
        }

        // round P to tf32 (unbiased) before feeding the PV mma
#pragma unroll
        for (int nt = 0; nt < 9; nt++)
#pragma unroll
            for (int r = 0; r < 4; r++) sacc[nt][r] = tf32r(sacc[nt][r]);

        // --- O += P V : P (regs) -> A-frags via quad shuffles; V via ldsm2 ---
#pragma unroll
        for (int ks = 0; ks < 9; ks++) {
            float v00 = __shfl_sync(0xffffffffu, sacc[ks][0], srcA);
            float v01 = __shfl_sync(0xffffffffu, sacc[ks][1], srcA);
            float v10 = __shfl_sync(0xffffffffu, sacc[ks][2], srcA);
            float v11 = __shfl_sync(0xffffffffu, sacc[ks][3], srcA);
            float v20 = __shfl_sync(0xffffffffu, sacc[ks][0], srcB);
            float v21 = __shfl_sync(0xffffffffu, sacc[ks][1], srcB);
            float v30 = __shfl_sync(0xffffffffu, sacc[ks][2], srcB);
            float v31 = __shfl_sync(0xffffffffu, sacc[ks][3], srcB);
            unsigned a0 = __float_as_uint((tg & 1) ? v01 : v00);
            unsigned a1 = __float_as_uint((tg & 1) ? v11 : v10);
            unsigned a2 = __float_as_uint((tg & 1) ? v21 : v20);
            unsigned a3 = __float_as_uint((tg & 1) ? v31 : v30);
            const int kcol = c0 + ks * 8 + ((lane & 8) ? 4 : 0);
#pragma unroll
            for (int ni = 0; ni < 4; ni++) {
                unsigned b0, b1;
                ldsm2(b0, b1, sptr(Vt + (ni * 8 + (lane & 7)) * 148 + kcol));
                mma8(oacc[ni], a0, a1, a2, a3, b0, b1);
            }
        }
    }

    // ---- normalize and store ----
    const float inv0 = 1.f / lr0;
    const float inv1 = 1.f / lr1;
#pragma unroll
    for (int ni = 0; ni < 4; ni++) {
        int d = ni * 8 + tg * 2;
        *(float2*)(outp + (size_t)r0 * CDIM + d) =
            make_float2(oacc[ni][0] * inv0, oacc[ni][1] * inv0);
        *(float2*)(outp + (size_t)r1 * CDIM + d) =
            make_float2(oacc[ni][2] * inv1, oacc[ni][3] * inv1);
    }
}

// ---------------- kernel 3: out = att @ W2 + b2 ----------------
__global__ __launch_bounds__(384) void k_proj(const float* __restrict__ W2,
                                              const float* __restrict__ b2,
                                              float* __restrict__ out) {
    extern __shared__ __align__(16) float smg[];
    float* As = smg;
    float* Bs = smg + 2 * 128 * 36;

    const int tid  = threadIdx.x;
    const int lane = tid & 31, wid = tid >> 5;
    const int g = lane >> 2, tg = lane & 3;
    const int wm = wid & 3, wn = wid >> 2;
    const int mblk = blockIdx.x * 128;

    float4 ra[3], rb[4];
#pragma unroll
    for (int i = 0; i < 3; i++) {
        int idx = tid + 384 * i;
        if (idx < 1024) {
            int r = idx >> 3, kc = (idx & 7) << 2;
            ra[i] = *(const float4*)(g_att + (size_t)(mblk + r) * CDIM + kc);
        }
    }
#pragma unroll
    for (int i = 0; i < 4; i++) {
        int idx = tid + 384 * i;
        int kr = idx / 48, nc = (idx % 48) << 2;
        rb[i] = *(const float4*)(W2 + (size_t)kr * CDIM + nc);
    }
#pragma unroll
    for (int i = 0; i < 3; i++) {
        int idx = tid + 384 * i;
        if (idx < 1024) {
            int r = idx >> 3, kc = (idx & 7) << 2;
            *(float4*)&As[(size_t)r * 36 + kc] = tf32r4(ra[i]);
        }
    }
#pragma unroll
    for (int i = 0; i < 4; i++) {
        int idx = tid + 384 * i;
        int kr = idx / 48, nc = (idx % 48) << 2;
        *(float4*)&Bs[(size_t)kr * 200 + nc] = tf32r4(rb[i]);
    }
    __syncthreads();

    float acc[2][8][4];
#pragma unroll
    for (int i = 0; i < 2; i++)
#pragma unroll
        for (int j = 0; j < 8; j++)
#pragma unroll
            for (int r = 0; r < 4; r++) acc[i][j][r] = 0.f;

    for (int kt = 0; kt < 6; kt++) {
        const int cur = kt & 1;
        float* Ac = As + (size_t)cur * (128 * 36);
        float* Bc = Bs + (size_t)cur * (32 * 200);
        if (kt < 5) {
            const int k0 = (kt + 1) * 32;
#pragma unroll
            for (int i = 0; i < 3; i++) {
                int idx = tid + 384 * i;
                if (idx < 1024) {
                    int r = idx >> 3, kc = (idx & 7) << 2;
                    ra[i] = *(const float4*)(g_att + (size_t)(mblk + r) * CDIM + k0 + kc);
                }
            }
#pragma unroll
            for (int i = 0; i < 4; i++) {
                int idx = tid + 384 * i;
                int kr = idx / 48, nc = (idx % 48) << 2;
                rb[i] = *(const float4*)(W2 + (size_t)(k0 + kr) * CDIM + nc);
            }
        }
#pragma unroll
        for (int kk = 0; kk < 4; kk++) {
            const int kb = kk * 8;
            unsigned a[2][4];
#pragma unroll
            for (int mi = 0; mi < 2; mi++) {
                int arow = wm * 32 + mi * 16 + (lane & 15);
                int acol = kb + ((lane & 16) ? 4 : 0);
                ldsm4(a[mi][0], a[mi][1], a[mi][2], a[mi][3], sptr(Ac + arow * 36 + acol));
            }
#pragma unroll
            for (int ni = 0; ni < 8; ni++) {
                int c0 = wn * 64 + ni * 8;
                unsigned b0 = __float_as_uint(Bc[(kb + tg) * 200 + c0 + g]);
                unsigned b1 = __float_as_uint(Bc[(kb + tg + 4) * 200 + c0 + g]);
#pragma unroll
                for (int mi = 0; mi < 2; mi++)
                    mma8(acc[mi][ni], a[mi][0], a[mi][1], a[mi][2], a[mi][3], b0, b1);
            }
        }
        if (kt < 5) {
            float* An = As + (size_t)(cur ^ 1) * (128 * 36);
            float* Bn = Bs + (size_t)(cur ^ 1) * (32 * 200);
#pragma unroll
            for (int i = 0; i < 3; i++) {
                int idx = tid + 384 * i;
                if (idx < 1024) {
                    int r = idx >> 3, kc = (idx & 7) << 2;
                    *(float4*)&An[(size_t)r * 36 + kc] = tf32r4(ra[i]);
                }
            }
#pragma unroll
            for (int i = 0; i < 4; i++) {
                int idx = tid + 384 * i;
                int kr = idx / 48, nc = (idx % 48) << 2;
                *(float4*)&Bn[(size_t)kr * 200 + nc] = tf32r4(rb[i]);
            }
        }
        __syncthreads();
    }

#pragma unroll
    for (int mi = 0; mi < 2; mi++)
#pragma unroll
        for (int ni = 0; ni < 8; ni++)
#pragma unroll
            for (int r2 = 0; r2 < 2; r2++) {
                int mrow = mblk + wm * 32 + mi * 16 + g + r2 * 8;
                int n    = wn * 64 + ni * 8 + tg * 2;
                float v0 = acc[mi][ni][r2 * 2 + 0] + b2[n];
                float v1 = acc[mi][ni][r2 * 2 + 1] + b2[n + 1];
                *(float2*)(out + (size_t)mrow * CDIM + n) = make_float2(v0, v1);
            }
}

// ---------------- launch ----------------
extern "C" void kernel_launch(void* const* d_in, const int* in_sizes, int n_in,
                              void* d_out, int out_size) {
    const float* x     = (const float*)d_in[0];
    const float* mask  = (const float*)d_in[1];
    const float* W1    = (const float*)d_in[2];
    const float* b1    = (const float*)d_in[3];
    const float* W2    = (const float*)d_in[4];
    const float* b2    = (const float*)d_in[5];
    const float* table = (const float*)d_in[6];
    const int*   pidx  = (const int*)d_in[7];

    cudaFuncSetAttribute(k_attn, cudaFuncAttributeMaxDynamicSharedMemorySize, SMEM_ATT);
    cudaFuncSetAttribute(k_qkv,  cudaFuncAttributeMaxDynamicSharedMemorySize, GEMM_SMEM);
    cudaFuncSetAttribute(k_proj, cudaFuncAttributeMaxDynamicSharedMemorySize, GEMM_SMEM);

    k_bias<<<(NW * HEADS * LW * LW + 255) / 256, 256>>>(table, pidx);
    k_qkv<<<dim3(N1 / 192, M1 / 128), 384, GEMM_SMEM>>>(x, W1, b1);
    k_attn<<<dim3(HEADS, BTOT), 288, SMEM_ATT>>>(mask);
    k_proj<<<M1 / 128, 384, GEMM_SMEM>>>(W2, b2, (float*)d_out);
}